// round 8
// baseline (speedup 1.0000x reference)
#include <cuda_runtime.h>
#include <math.h>
#include <float.h>

#define NN 100000
#define EE 1600000
#define IN_F 256
#define HH 4
#define DD 32
#define CC 47
#define HD 128        // H*D
#define HC 188        // H*C
#define NEG_SLOPE 0.2f
#define FULLMASK 0xffffffffu

// ---------------- scratch (static device globals; no allocation) ------------
__device__ __align__(16) float g_feat[(size_t)NN * HC];
__device__ __align__(16) float g_hbuf[(size_t)NN * HD];
__device__ __align__(16) float g_el[NN * HH];
__device__ __align__(16) float g_er[NN * HH];
__device__ int g_deg[NN];
__device__ int g_off[NN + 1];
__device__ int g_cur[NN];
__device__ int g_esrc[EE];

// ---------------- warp helpers ----------------------------------------------
__device__ __forceinline__ float warpsum(float v) {
#pragma unroll
    for (int o = 16; o; o >>= 1) v += __shfl_xor_sync(FULLMASK, v, o);
    return v;
}
__device__ __forceinline__ float warpmax(float v) {
#pragma unroll
    for (int o = 16; o; o >>= 1) v = fmaxf(v, __shfl_xor_sync(FULLMASK, v, o));
    return v;
}
__device__ __forceinline__ float lrelu(float v) {
    return v > 0.f ? v : NEG_SLOPE * v;
}
__device__ __forceinline__ unsigned f2tf(float x) {
    unsigned r;
    asm("cvt.rna.tf32.f32 %0, %1;" : "=r"(r) : "f"(x));
    return r;
}

// ---------------- CSR build --------------------------------------------------
__global__ void zero_deg_kernel() {
    int i = blockIdx.x * blockDim.x + threadIdx.x;
    if (i < NN) g_deg[i] = 0;
}
__global__ void hist_kernel(const int* __restrict__ dst) {
    int e = blockIdx.x * blockDim.x + threadIdx.x;
    if (e < EE) atomicAdd(&g_deg[dst[e]], 1);
}
__global__ void scan_kernel() {
    __shared__ int warpsums[32];
    __shared__ int s_carry;
    int tid = threadIdx.x;
    int lane = tid & 31, wid = tid >> 5;
    if (tid == 0) s_carry = 0;
    __syncthreads();
    for (int base = 0; base < NN; base += 1024) {
        int i = base + tid;
        int v = (i < NN) ? g_deg[i] : 0;
        int x = v;
#pragma unroll
        for (int o = 1; o < 32; o <<= 1) {
            int t = __shfl_up_sync(FULLMASK, x, o);
            if (lane >= o) x += t;
        }
        if (lane == 31) warpsums[wid] = x;
        __syncthreads();
        if (wid == 0) {
            int w = warpsums[lane];
#pragma unroll
            for (int o = 1; o < 32; o <<= 1) {
                int t = __shfl_up_sync(FULLMASK, w, o);
                if (lane >= o) w += t;
            }
            warpsums[lane] = w;
        }
        __syncthreads();
        int warpoff = (wid == 0) ? 0 : warpsums[wid - 1];
        int incl = x + warpoff;
        int excl = incl - v;
        int carry = s_carry;
        if (i < NN) { g_off[i] = carry + excl; g_cur[i] = carry + excl; }
        __syncthreads();
        if (tid == 1023) s_carry = carry + incl;
        __syncthreads();
    }
    if (tid == 0) g_off[NN] = s_carry;
}
__global__ void scatter_kernel(const int* __restrict__ src,
                               const int* __restrict__ dst) {
    int e = blockIdx.x * blockDim.x + threadIdx.x;
    if (e >= EE) return;
    int p = atomicAdd(&g_cur[dst[e]], 1);
    g_esrc[p] = src[e];
}

// ---------------- 3xTF32 tensor-core GEMM -----------------------------------
#define GBM 128
#define GBN 64
#define GBK 16
#define ASTR (GBM + 8)
#define BSTR (GBN + 8)

__device__ __forceinline__ void mma_tf32(float* c, const unsigned* a, const unsigned* b) {
    asm("mma.sync.aligned.m16n8k8.row.col.f32.tf32.tf32.f32 "
        "{%0,%1,%2,%3}, {%4,%5,%6,%7}, {%8,%9}, {%0,%1,%2,%3};"
        : "+f"(c[0]), "+f"(c[1]), "+f"(c[2]), "+f"(c[3])
        : "r"(a[0]), "r"(a[1]), "r"(a[2]), "r"(a[3]), "r"(b[0]), "r"(b[1]));
}

__global__ void __launch_bounds__(256, 2)
tf32_gemm_kernel(const float* __restrict__ Aext,
                 const float* __restrict__ B,
                 int M, int K, int Kn, int use_hbuf) {
    __shared__ unsigned Ah[GBK][ASTR], Al[GBK][ASTR];
    __shared__ unsigned Bh[GBK][BSTR], Bl[GBK][BSTR];

    const float* __restrict__ A = use_hbuf ? (const float*)g_hbuf : Aext;

    int tid = threadIdx.x;
    int wid = tid >> 5, lane = tid & 31;
    int row0 = blockIdx.y * GBM, col0 = blockIdx.x * GBN;
    int m0 = (wid >> 1) * 32;
    int n0 = (wid & 1) * 32;
    int gq = lane >> 2;
    int tg = lane & 3;

    int a_m = tid >> 1;
    int a_k = (tid & 1) * 8;
    int b_k = tid >> 4;
    int b_n = (tid & 15) * 4;

    float aS[8];
    float bS[4];

    auto loadG = [&](int k0) {
        int row = row0 + a_m;
        if (row < M) {
            const float* ap = A + (size_t)row * K + k0 + a_k;
            float4 v0 = *(const float4*)(ap);
            float4 v1 = *(const float4*)(ap + 4);
            aS[0] = v0.x; aS[1] = v0.y; aS[2] = v0.z; aS[3] = v0.w;
            aS[4] = v1.x; aS[5] = v1.y; aS[6] = v1.z; aS[7] = v1.w;
        } else {
#pragma unroll
            for (int j = 0; j < 8; j++) aS[j] = 0.f;
        }
        int col = col0 + b_n;
        const float* bp = B + (size_t)(k0 + b_k) * Kn;
        if (col + 3 < Kn) {
            float4 v = *(const float4*)(bp + col);
            bS[0] = v.x; bS[1] = v.y; bS[2] = v.z; bS[3] = v.w;
        } else {
#pragma unroll
            for (int j = 0; j < 4; j++) bS[j] = (col + j < Kn) ? bp[col + j] : 0.f;
        }
    };
    auto storeS = [&]() {
#pragma unroll
        for (int j = 0; j < 8; j++) {
            unsigned h = f2tf(aS[j]);
            Ah[a_k + j][a_m] = h;
            Al[a_k + j][a_m] = f2tf(aS[j] - __uint_as_float(h));
        }
#pragma unroll
        for (int j = 0; j < 4; j++) {
            unsigned h = f2tf(bS[j]);
            Bh[b_k][b_n + j] = h;
            Bl[b_k][b_n + j] = f2tf(bS[j] - __uint_as_float(h));
        }
    };

    float acc[2][4][4];
#pragma unroll
    for (int mi = 0; mi < 2; mi++)
#pragma unroll
        for (int ni = 0; ni < 4; ni++)
#pragma unroll
            for (int r = 0; r < 4; r++) acc[mi][ni][r] = 0.f;

    loadG(0);
    storeS();
    __syncthreads();

    for (int k0 = 0; k0 < K; k0 += GBK) {
        bool more = (k0 + GBK < K);
        if (more) loadG(k0 + GBK);
#pragma unroll
        for (int kk = 0; kk < GBK; kk += 8) {
            unsigned aHf[2][4], aLf[2][4];
#pragma unroll
            for (int mi = 0; mi < 2; mi++) {
                int mr = m0 + mi * 16 + gq;
                aHf[mi][0] = Ah[kk + tg][mr];
                aHf[mi][1] = Ah[kk + tg][mr + 8];
                aHf[mi][2] = Ah[kk + 4 + tg][mr];
                aHf[mi][3] = Ah[kk + 4 + tg][mr + 8];
                aLf[mi][0] = Al[kk + tg][mr];
                aLf[mi][1] = Al[kk + tg][mr + 8];
                aLf[mi][2] = Al[kk + 4 + tg][mr];
                aLf[mi][3] = Al[kk + 4 + tg][mr + 8];
            }
            unsigned bHf[4][2], bLf[4][2];
#pragma unroll
            for (int ni = 0; ni < 4; ni++) {
                int bc = n0 + ni * 8 + gq;
                bHf[ni][0] = Bh[kk + tg][bc];
                bHf[ni][1] = Bh[kk + 4 + tg][bc];
                bLf[ni][0] = Bl[kk + tg][bc];
                bLf[ni][1] = Bl[kk + 4 + tg][bc];
            }
#pragma unroll
            for (int mi = 0; mi < 2; mi++)
#pragma unroll
                for (int ni = 0; ni < 4; ni++) {
                    mma_tf32(acc[mi][ni], aHf[mi], bHf[ni]);
                    mma_tf32(acc[mi][ni], aHf[mi], bLf[ni]);
                    mma_tf32(acc[mi][ni], aLf[mi], bHf[ni]);
                }
        }
        if (more) {
            __syncthreads();
            storeS();
            __syncthreads();
        }
    }

#pragma unroll
    for (int mi = 0; mi < 2; mi++) {
        int r0 = row0 + m0 + mi * 16 + gq;
#pragma unroll
        for (int ni = 0; ni < 4; ni++) {
            int c = col0 + n0 + ni * 8 + tg * 2;
            if (c < Kn) {
                if (r0 < M) {
                    float2 v = make_float2(acc[mi][ni][0], acc[mi][ni][1]);
                    *(float2*)(g_feat + (size_t)r0 * Kn + c) = v;
                }
                if (r0 + 8 < M) {
                    float2 v = make_float2(acc[mi][ni][2], acc[mi][ni][3]);
                    *(float2*)(g_feat + (size_t)(r0 + 8) * Kn + c) = v;
                }
            }
        }
    }
}

// ---------------- per-node attention projections (el, er) -------------------
__global__ void elr_kernel(const float* __restrict__ al,
                           const float* __restrict__ ar,
                           int F) {
    int w = (blockIdx.x * blockDim.x + threadIdx.x) >> 5;
    int lane = threadIdx.x & 31;
    if (w >= NN) return;
    const float* frow = g_feat + (size_t)w * HH * F;
#pragma unroll
    for (int h = 0; h < HH; h++) {
        float sl = 0.f, sr = 0.f;
        for (int d = lane; d < F; d += 32) {
            float f = frow[h * F + d];
            sl = fmaf(f, al[h * F + d], sl);
            sr = fmaf(f, ar[h * F + d], sr);
        }
        sl = warpsum(sl);
        sr = warpsum(sr);
        if (lane == 0) {
            g_el[w * HH + h] = sl;
            g_er[w * HH + h] = sr;
        }
    }
}

// ---------------- fused softmax + aggregation ---------------------------------
// One warp per dst node. Phase A: per-edge normalized alphas staged in SMEM.
// Phase B: ILP-unrolled gather with broadcast LDS (no shfl serialization).
#define NCH 4
#define CHCAP (NCH * 32)   // 128 cached edges per node

__global__ void __launch_bounds__(256)
aggr128_kernel(const float* __restrict__ bias) {
    __shared__ int    s_src[8][CHCAP];
    __shared__ float4 s_w[8][CHCAP];
    int node = (blockIdx.x * blockDim.x + threadIdx.x) >> 5;
    int lane = threadIdx.x & 31;
    int wslot = (threadIdx.x >> 5);
    if (node >= NN) return;
    int beg = g_off[node], end = g_off[node + 1];
    int deg = end - beg;
    float4 er4 = *(const float4*)(g_er + (size_t)node * 4);
    int nch = (deg + 31) >> 5; if (nch > NCH) nch = NCH;

    // Phase A: exps into smem + denominator
    float d0 = 0.f, d1 = 0.f, d2 = 0.f, d3 = 0.f;
#pragma unroll
    for (int c = 0; c < NCH; c++) {
        if (c < nch) {
            int idx = c * 32 + lane;
            int p = beg + idx;
            if (p < end) {
                int s = g_esrc[p];
                float4 el4 = *(const float4*)(g_el + (size_t)s * 4);
                float e0 = __expf(lrelu(el4.x + er4.x));
                float e1 = __expf(lrelu(el4.y + er4.y));
                float e2 = __expf(lrelu(el4.z + er4.z));
                float e3 = __expf(lrelu(el4.w + er4.w));
                s_src[wslot][idx] = s;
                s_w[wslot][idx] = make_float4(e0, e1, e2, e3);
                d0 += e0; d1 += e1; d2 += e2; d3 += e3;
            }
        }
    }
    for (int p = beg + CHCAP + lane; p < end; p += 32) {
        int s = g_esrc[p];
        float4 el4 = *(const float4*)(g_el + (size_t)s * 4);
        d0 += __expf(lrelu(el4.x + er4.x));
        d1 += __expf(lrelu(el4.y + er4.y));
        d2 += __expf(lrelu(el4.z + er4.z));
        d3 += __expf(lrelu(el4.w + er4.w));
    }
    d0 = warpsum(d0); d1 = warpsum(d1); d2 = warpsum(d2); d3 = warpsum(d3);
    float i0 = 1.f / d0, i1 = 1.f / d1, i2 = 1.f / d2, i3 = 1.f / d3;
    __syncwarp();
    // normalize own smem entries
#pragma unroll
    for (int c = 0; c < NCH; c++) {
        if (c < nch) {
            int idx = c * 32 + lane;
            if (beg + idx < end) {
                float4 w = s_w[wslot][idx];
                w.x *= i0; w.y *= i1; w.z *= i2; w.w *= i3;
                s_w[wslot][idx] = w;
            }
        }
    }
    __syncwarp();

    // Phase B: 4-way unrolled gather, independent accumulators
    int h = lane >> 3;
    int cached = deg < CHCAP ? deg : CHCAP;
    float4 A0 = make_float4(0.f, 0.f, 0.f, 0.f), A1 = A0, A2 = A0, A3 = A0;
    const int* sp = s_src[wslot];
    const float4* wp = s_w[wslot];
    int j = 0;
    for (; j + 4 <= cached; j += 4) {
        int sj0 = sp[j], sj1 = sp[j + 1], sj2 = sp[j + 2], sj3 = sp[j + 3];
        float4 w0 = wp[j], w1 = wp[j + 1], w2 = wp[j + 2], w3 = wp[j + 3];
        float a0 = h == 0 ? w0.x : (h == 1 ? w0.y : (h == 2 ? w0.z : w0.w));
        float a1 = h == 0 ? w1.x : (h == 1 ? w1.y : (h == 2 ? w1.z : w1.w));
        float a2 = h == 0 ? w2.x : (h == 1 ? w2.y : (h == 2 ? w2.z : w2.w));
        float a3 = h == 0 ? w3.x : (h == 1 ? w3.y : (h == 2 ? w3.z : w3.w));
        float4 f0 = *(const float4*)(g_feat + (size_t)sj0 * HD + lane * 4);
        float4 f1 = *(const float4*)(g_feat + (size_t)sj1 * HD + lane * 4);
        float4 f2 = *(const float4*)(g_feat + (size_t)sj2 * HD + lane * 4);
        float4 f3 = *(const float4*)(g_feat + (size_t)sj3 * HD + lane * 4);
        A0.x = fmaf(a0, f0.x, A0.x); A0.y = fmaf(a0, f0.y, A0.y);
        A0.z = fmaf(a0, f0.z, A0.z); A0.w = fmaf(a0, f0.w, A0.w);
        A1.x = fmaf(a1, f1.x, A1.x); A1.y = fmaf(a1, f1.y, A1.y);
        A1.z = fmaf(a1, f1.z, A1.z); A1.w = fmaf(a1, f1.w, A1.w);
        A2.x = fmaf(a2, f2.x, A2.x); A2.y = fmaf(a2, f2.y, A2.y);
        A2.z = fmaf(a2, f2.z, A2.z); A2.w = fmaf(a2, f2.w, A2.w);
        A3.x = fmaf(a3, f3.x, A3.x); A3.y = fmaf(a3, f3.y, A3.y);
        A3.z = fmaf(a3, f3.z, A3.z); A3.w = fmaf(a3, f3.w, A3.w);
    }
    for (; j < cached; j++) {
        int sj = sp[j];
        float4 w = wp[j];
        float a = h == 0 ? w.x : (h == 1 ? w.y : (h == 2 ? w.z : w.w));
        float4 f = *(const float4*)(g_feat + (size_t)sj * HD + lane * 4);
        A0.x = fmaf(a, f.x, A0.x); A0.y = fmaf(a, f.y, A0.y);
        A0.z = fmaf(a, f.z, A0.z); A0.w = fmaf(a, f.w, A0.w);
    }
    // tail: deg > CHCAP (rare) — recompute alphas via shfl
    for (int base = beg + CHCAP; base < end; base += 32) {
        int p = base + lane;
        int cnt = min(32, end - base);
        int s = 0; float x0 = 0.f, x1 = 0.f, x2 = 0.f, x3 = 0.f;
        if (p < end) {
            s = g_esrc[p];
            float4 el4 = *(const float4*)(g_el + (size_t)s * 4);
            x0 = __expf(lrelu(el4.x + er4.x)) * i0;
            x1 = __expf(lrelu(el4.y + er4.y)) * i1;
            x2 = __expf(lrelu(el4.z + er4.z)) * i2;
            x3 = __expf(lrelu(el4.w + er4.w)) * i3;
        }
        for (int q = 0; q < cnt; q++) {
            int sj = __shfl_sync(FULLMASK, s, q);
            float w0 = __shfl_sync(FULLMASK, x0, q);
            float w1 = __shfl_sync(FULLMASK, x1, q);
            float w2 = __shfl_sync(FULLMASK, x2, q);
            float w3 = __shfl_sync(FULLMASK, x3, q);
            float a = h == 0 ? w0 : (h == 1 ? w1 : (h == 2 ? w2 : w3));
            float4 f = *(const float4*)(g_feat + (size_t)sj * HD + lane * 4);
            A0.x = fmaf(a, f.x, A0.x); A0.y = fmaf(a, f.y, A0.y);
            A0.z = fmaf(a, f.z, A0.z); A0.w = fmaf(a, f.w, A0.w);
        }
    }

    float4 acc;
    acc.x = (A0.x + A1.x) + (A2.x + A3.x);
    acc.y = (A0.y + A1.y) + (A2.y + A3.y);
    acc.z = (A0.z + A1.z) + (A2.z + A3.z);
    acc.w = (A0.w + A1.w) + (A2.w + A3.w);
    float4 bv = *(const float4*)(bias + lane * 4);
    float4 o;
    o.x = fmaxf(acc.x + bv.x, 0.f);
    o.y = fmaxf(acc.y + bv.y, 0.f);
    o.z = fmaxf(acc.z + bv.z, 0.f);
    o.w = fmaxf(acc.w + bv.w, 0.f);
    *(float4*)(g_hbuf + (size_t)node * HD + lane * 4) = o;
}

// ---------------- fused softmax + aggr + head-mean + log_softmax, layer 3 ---
__global__ void __launch_bounds__(256)
aggr47_final_kernel(const float* __restrict__ b3,
                    float* __restrict__ out) {
    __shared__ int    s_src[8][CHCAP];
    __shared__ float4 s_w[8][CHCAP];
    int node = (blockIdx.x * blockDim.x + threadIdx.x) >> 5;
    int lane = threadIdx.x & 31;
    int wslot = (threadIdx.x >> 5);
    if (node >= NN) return;
    int beg = g_off[node], end = g_off[node + 1];
    int deg = end - beg;
    float4 er4 = *(const float4*)(g_er + (size_t)node * 4);
    int nch = (deg + 31) >> 5; if (nch > NCH) nch = NCH;

    float d0 = 0.f, d1 = 0.f, d2 = 0.f, d3 = 0.f;
#pragma unroll
    for (int c = 0; c < NCH; c++) {
        if (c < nch) {
            int idx = c * 32 + lane;
            int p = beg + idx;
            if (p < end) {
                int s = g_esrc[p];
                float4 el4 = *(const float4*)(g_el + (size_t)s * 4);
                float e0 = __expf(lrelu(el4.x + er4.x));
                float e1 = __expf(lrelu(el4.y + er4.y));
                float e2 = __expf(lrelu(el4.z + er4.z));
                float e3 = __expf(lrelu(el4.w + er4.w));
                s_src[wslot][idx] = s;
                s_w[wslot][idx] = make_float4(e0, e1, e2, e3);
                d0 += e0; d1 += e1; d2 += e2; d3 += e3;
            }
        }
    }
    for (int p = beg + CHCAP + lane; p < end; p += 32) {
        int s = g_esrc[p];
        float4 el4 = *(const float4*)(g_el + (size_t)s * 4);
        d0 += __expf(lrelu(el4.x + er4.x));
        d1 += __expf(lrelu(el4.y + er4.y));
        d2 += __expf(lrelu(el4.z + er4.z));
        d3 += __expf(lrelu(el4.w + er4.w));
    }
    d0 = warpsum(d0); d1 = warpsum(d1); d2 = warpsum(d2); d3 = warpsum(d3);
    float i0 = 1.f / d0, i1 = 1.f / d1, i2 = 1.f / d2, i3 = 1.f / d3;
    __syncwarp();
#pragma unroll
    for (int c = 0; c < NCH; c++) {
        if (c < nch) {
            int idx = c * 32 + lane;
            if (beg + idx < end) {
                float4 w = s_w[wslot][idx];
                w.x *= i0; w.y *= i1; w.z *= i2; w.w *= i3;
                s_w[wslot][idx] = w;
            }
        }
    }
    __syncwarp();

    // Phase B: 2-way unrolled, lane covers classes lane and lane+32
    int cached = deg < CHCAP ? deg : CHCAP;
    float a0A = 0.f, a0B = 0.f, a1A = 0.f, a1B = 0.f;
    const int* sp = s_src[wslot];
    const float4* wp = s_w[wslot];
    bool hi = (lane < CC - 32);
    int cx = 32 + lane;
    int j = 0;
    for (; j + 2 <= cached; j += 2) {
        int sj0 = sp[j], sj1 = sp[j + 1];
        float4 w0 = wp[j], w1 = wp[j + 1];
        const float* fr0 = g_feat + (size_t)sj0 * HC;
        const float* fr1 = g_feat + (size_t)sj1 * HC;
        a0A += w0.x * fr0[lane] + w0.y * fr0[CC + lane]
             + w0.z * fr0[2 * CC + lane] + w0.w * fr0[3 * CC + lane];
        a0B += w1.x * fr1[lane] + w1.y * fr1[CC + lane]
             + w1.z * fr1[2 * CC + lane] + w1.w * fr1[3 * CC + lane];
        if (hi) {
            a1A += w0.x * fr0[cx] + w0.y * fr0[CC + cx]
                 + w0.z * fr0[2 * CC + cx] + w0.w * fr0[3 * CC + cx];
            a1B += w1.x * fr1[cx] + w1.y * fr1[CC + cx]
                 + w1.z * fr1[2 * CC + cx] + w1.w * fr1[3 * CC + cx];
        }
    }
    for (; j < cached; j++) {
        int sj = sp[j];
        float4 w = wp[j];
        const float* fr = g_feat + (size_t)sj * HC;
        a0A += w.x * fr[lane] + w.y * fr[CC + lane]
             + w.z * fr[2 * CC + lane] + w.w * fr[3 * CC + lane];
        if (hi)
            a1A += w.x * fr[cx] + w.y * fr[CC + cx]
                 + w.z * fr[2 * CC + cx] + w.w * fr[3 * CC + cx];
    }
    // tail (deg > CHCAP, rare)
    for (int base = beg + CHCAP; base < end; base += 32) {
        int p = base + lane;
        int cnt = min(32, end - base);
        int s = 0; float x0 = 0.f, x1 = 0.f, x2 = 0.f, x3 = 0.f;
        if (p < end) {
            s = g_esrc[p];
            float4 el4 = *(const float4*)(g_el + (size_t)s * 4);
            x0 = __expf(lrelu(el4.x + er4.x)) * i0;
            x1 = __expf(lrelu(el4.y + er4.y)) * i1;
            x2 = __expf(lrelu(el4.z + er4.z)) * i2;
            x3 = __expf(lrelu(el4.w + er4.w)) * i3;
        }
        for (int q = 0; q < cnt; q++) {
            int sj = __shfl_sync(FULLMASK, s, q);
            float w0 = __shfl_sync(FULLMASK, x0, q);
            float w1 = __shfl_sync(FULLMASK, x1, q);
            float w2 = __shfl_sync(FULLMASK, x2, q);
            float w3 = __shfl_sync(FULLMASK, x3, q);
            const float* fr = g_feat + (size_t)sj * HC;
            a0A += w0 * fr[lane] + w1 * fr[CC + lane]
                 + w2 * fr[2 * CC + lane] + w3 * fr[3 * CC + lane];
            if (hi)
                a1A += w0 * fr[cx] + w1 * fr[CC + cx]
                     + w2 * fr[2 * CC + cx] + w3 * fr[3 * CC + cx];
        }
    }

    float a0 = a0A + a0B, a1 = a1A + a1B;
    float v0 = a0 * 0.25f + 0.25f * (b3[lane] + b3[CC + lane] +
                                     b3[2 * CC + lane] + b3[3 * CC + lane]);
    float v1 = 0.f;
    if (hi)
        v1 = a1 * 0.25f + 0.25f * (b3[cx] + b3[CC + cx] +
                                   b3[2 * CC + cx] + b3[3 * CC + cx]);
    float mm = v0;
    if (hi) mm = fmaxf(mm, v1);
    mm = warpmax(mm);
    float s = __expf(v0 - mm);
    if (hi) s += __expf(v1 - mm);
    s = warpsum(s);
    float lse = logf(s) + mm;
    out[(size_t)node * CC + lane] = v0 - lse;
    if (hi) out[(size_t)node * CC + cx] = v1 - lse;
}

// ---------------- host orchestration ----------------------------------------
extern "C" void kernel_launch(void* const* d_in, const int* in_sizes, int n_in,
                              void* d_out, int out_size) {
    const float* x   = (const float*)d_in[0];
    const int*   src = (const int*)  d_in[1];
    const int*   dst = (const int*)  d_in[2];
    const float* W1  = (const float*)d_in[3];
    const float* al1 = (const float*)d_in[4];
    const float* ar1 = (const float*)d_in[5];
    const float* b1  = (const float*)d_in[6];
    const float* W2  = (const float*)d_in[7];
    const float* al2 = (const float*)d_in[8];
    const float* ar2 = (const float*)d_in[9];
    const float* b2  = (const float*)d_in[10];
    const float* W3  = (const float*)d_in[11];
    const float* al3 = (const float*)d_in[12];
    const float* ar3 = (const float*)d_in[13];
    const float* b3  = (const float*)d_in[14];
    float* out = (float*)d_out;

    // ---- CSR build (same graph for all 3 layers) ----
    zero_deg_kernel<<<(NN + 255) / 256, 256>>>();
    hist_kernel<<<(EE + 255) / 256, 256>>>(dst);
    scan_kernel<<<1, 1024>>>();
    scatter_kernel<<<(EE + 255) / 256, 256>>>(src, dst);

    int node_warp_blocks = (NN * 32 + 255) / 256;
    int mblocks = (NN + GBM - 1) / GBM;

    // ---- Layer 1: IN -> H*D, ReLU ----
    tf32_gemm_kernel<<<dim3(2, mblocks), 256>>>(x, W1, NN, IN_F, HD, 0);
    elr_kernel<<<node_warp_blocks, 256>>>(al1, ar1, DD);
    aggr128_kernel<<<node_warp_blocks, 256>>>(b1);

    // ---- Layer 2: H*D -> H*D, ReLU ----
    tf32_gemm_kernel<<<dim3(2, mblocks), 256>>>(nullptr, W2, NN, HD, HD, 1);
    elr_kernel<<<node_warp_blocks, 256>>>(al2, ar2, DD);
    aggr128_kernel<<<node_warp_blocks, 256>>>(b2);

    // ---- Layer 3: H*D -> H*C, head-mean + log_softmax ----
    tf32_gemm_kernel<<<dim3(3, mblocks), 256>>>(nullptr, W3, NN, HD, HC, 1);
    elr_kernel<<<node_warp_blocks, 256>>>(al3, ar3, CC);
    aggr47_final_kernel<<<node_warp_blocks, 256>>>(b3, out);
}

// round 10
// speedup vs baseline: 1.1771x; 1.1771x over previous
#include <cuda_runtime.h>
#include <math.h>
#include <float.h>

#define NN 100000
#define EE 1600000
#define IN_F 256
#define HH 4
#define DD 32
#define CC 47
#define HD 128        // H*D
#define HC 188        // H*C
#define NEG_SLOPE 0.2f
#define FULLMASK 0xffffffffu

// ---------------- scratch (static device globals; no allocation) ------------
__device__ __align__(16) float g_feat[(size_t)NN * HC];
__device__ __align__(16) float g_hbuf[(size_t)NN * HD];
__device__ __align__(16) float g_el[NN * HH];
__device__ __align__(16) float g_er[NN * HH];
__device__ int g_deg[NN];
__device__ int g_off[NN + 1];
__device__ int g_cur[NN];
__device__ int g_esrc[EE];

// ---------------- warp helpers ----------------------------------------------
__device__ __forceinline__ float warpsum(float v) {
#pragma unroll
    for (int o = 16; o; o >>= 1) v += __shfl_xor_sync(FULLMASK, v, o);
    return v;
}
__device__ __forceinline__ float warpmax(float v) {
#pragma unroll
    for (int o = 16; o; o >>= 1) v = fmaxf(v, __shfl_xor_sync(FULLMASK, v, o));
    return v;
}
__device__ __forceinline__ float lrelu(float v) {
    return v > 0.f ? v : NEG_SLOPE * v;
}
__device__ __forceinline__ unsigned f2tf(float x) {
    unsigned r;
    asm("cvt.rna.tf32.f32 %0, %1;" : "=r"(r) : "f"(x));
    return r;
}

// ---------------- CSR build --------------------------------------------------
__global__ void zero_deg_kernel() {
    int i = blockIdx.x * blockDim.x + threadIdx.x;
    if (i < NN) g_deg[i] = 0;
}
__global__ void hist_kernel(const int* __restrict__ dst) {
    int e = blockIdx.x * blockDim.x + threadIdx.x;
    if (e < EE) atomicAdd(&g_deg[dst[e]], 1);
}
__global__ void scan_kernel() {
    __shared__ int warpsums[32];
    __shared__ int s_carry;
    int tid = threadIdx.x;
    int lane = tid & 31, wid = tid >> 5;
    if (tid == 0) s_carry = 0;
    __syncthreads();
    for (int base = 0; base < NN; base += 1024) {
        int i = base + tid;
        int v = (i < NN) ? g_deg[i] : 0;
        int x = v;
#pragma unroll
        for (int o = 1; o < 32; o <<= 1) {
            int t = __shfl_up_sync(FULLMASK, x, o);
            if (lane >= o) x += t;
        }
        if (lane == 31) warpsums[wid] = x;
        __syncthreads();
        if (wid == 0) {
            int w = warpsums[lane];
#pragma unroll
            for (int o = 1; o < 32; o <<= 1) {
                int t = __shfl_up_sync(FULLMASK, w, o);
                if (lane >= o) w += t;
            }
            warpsums[lane] = w;
        }
        __syncthreads();
        int warpoff = (wid == 0) ? 0 : warpsums[wid - 1];
        int incl = x + warpoff;
        int excl = incl - v;
        int carry = s_carry;
        if (i < NN) { g_off[i] = carry + excl; g_cur[i] = carry + excl; }
        __syncthreads();
        if (tid == 1023) s_carry = carry + incl;
        __syncthreads();
    }
    if (tid == 0) g_off[NN] = s_carry;
}
__global__ void scatter_kernel(const int* __restrict__ src,
                               const int* __restrict__ dst) {
    int e = blockIdx.x * blockDim.x + threadIdx.x;
    if (e >= EE) return;
    int p = atomicAdd(&g_cur[dst[e]], 1);
    g_esrc[p] = src[e];
}

// ---------------- 3xTF32 tensor-core GEMM -----------------------------------
#define GBM 128
#define GBN 64
#define GBK 16
#define ASTR (GBM + 8)
#define BSTR (GBN + 8)

__device__ __forceinline__ void mma_tf32(float* c, const unsigned* a, const unsigned* b) {
    asm("mma.sync.aligned.m16n8k8.row.col.f32.tf32.tf32.f32 "
        "{%0,%1,%2,%3}, {%4,%5,%6,%7}, {%8,%9}, {%0,%1,%2,%3};"
        : "+f"(c[0]), "+f"(c[1]), "+f"(c[2]), "+f"(c[3])
        : "r"(a[0]), "r"(a[1]), "r"(a[2]), "r"(a[3]), "r"(b[0]), "r"(b[1]));
}

__global__ void __launch_bounds__(256, 2)
tf32_gemm_kernel(const float* __restrict__ Aext,
                 const float* __restrict__ B,
                 int M, int K, int Kn, int use_hbuf) {
    __shared__ unsigned Ah[GBK][ASTR], Al[GBK][ASTR];
    __shared__ unsigned Bh[GBK][BSTR], Bl[GBK][BSTR];

    const float* __restrict__ A = use_hbuf ? (const float*)g_hbuf : Aext;

    int tid = threadIdx.x;
    int wid = tid >> 5, lane = tid & 31;
    int row0 = blockIdx.y * GBM, col0 = blockIdx.x * GBN;
    int m0 = (wid >> 1) * 32;
    int n0 = (wid & 1) * 32;
    int gq = lane >> 2;
    int tg = lane & 3;

    int a_m = tid >> 1;
    int a_k = (tid & 1) * 8;
    int b_k = tid >> 4;
    int b_n = (tid & 15) * 4;

    float aS[8];
    float bS[4];

    auto loadG = [&](int k0) {
        int row = row0 + a_m;
        if (row < M) {
            const float* ap = A + (size_t)row * K + k0 + a_k;
            float4 v0 = *(const float4*)(ap);
            float4 v1 = *(const float4*)(ap + 4);
            aS[0] = v0.x; aS[1] = v0.y; aS[2] = v0.z; aS[3] = v0.w;
            aS[4] = v1.x; aS[5] = v1.y; aS[6] = v1.z; aS[7] = v1.w;
        } else {
#pragma unroll
            for (int j = 0; j < 8; j++) aS[j] = 0.f;
        }
        int col = col0 + b_n;
        const float* bp = B + (size_t)(k0 + b_k) * Kn;
        if (col + 3 < Kn) {
            float4 v = *(const float4*)(bp + col);
            bS[0] = v.x; bS[1] = v.y; bS[2] = v.z; bS[3] = v.w;
        } else {
#pragma unroll
            for (int j = 0; j < 4; j++) bS[j] = (col + j < Kn) ? bp[col + j] : 0.f;
        }
    };
    auto storeS = [&]() {
#pragma unroll
        for (int j = 0; j < 8; j++) {
            unsigned h = f2tf(aS[j]);
            Ah[a_k + j][a_m] = h;
            Al[a_k + j][a_m] = f2tf(aS[j] - __uint_as_float(h));
        }
#pragma unroll
        for (int j = 0; j < 4; j++) {
            unsigned h = f2tf(bS[j]);
            Bh[b_k][b_n + j] = h;
            Bl[b_k][b_n + j] = f2tf(bS[j] - __uint_as_float(h));
        }
    };

    float acc[2][4][4];
#pragma unroll
    for (int mi = 0; mi < 2; mi++)
#pragma unroll
        for (int ni = 0; ni < 4; ni++)
#pragma unroll
            for (int r = 0; r < 4; r++) acc[mi][ni][r] = 0.f;

    loadG(0);
    storeS();
    __syncthreads();

    for (int k0 = 0; k0 < K; k0 += GBK) {
        bool more = (k0 + GBK < K);
        if (more) loadG(k0 + GBK);
#pragma unroll
        for (int kk = 0; kk < GBK; kk += 8) {
            unsigned aHf[2][4], aLf[2][4];
#pragma unroll
            for (int mi = 0; mi < 2; mi++) {
                int mr = m0 + mi * 16 + gq;
                aHf[mi][0] = Ah[kk + tg][mr];
                aHf[mi][1] = Ah[kk + tg][mr + 8];
                aHf[mi][2] = Ah[kk + 4 + tg][mr];
                aHf[mi][3] = Ah[kk + 4 + tg][mr + 8];
                aLf[mi][0] = Al[kk + tg][mr];
                aLf[mi][1] = Al[kk + tg][mr + 8];
                aLf[mi][2] = Al[kk + 4 + tg][mr];
                aLf[mi][3] = Al[kk + 4 + tg][mr + 8];
            }
            unsigned bHf[4][2], bLf[4][2];
#pragma unroll
            for (int ni = 0; ni < 4; ni++) {
                int bc = n0 + ni * 8 + gq;
                bHf[ni][0] = Bh[kk + tg][bc];
                bHf[ni][1] = Bh[kk + 4 + tg][bc];
                bLf[ni][0] = Bl[kk + tg][bc];
                bLf[ni][1] = Bl[kk + 4 + tg][bc];
            }
#pragma unroll
            for (int mi = 0; mi < 2; mi++)
#pragma unroll
                for (int ni = 0; ni < 4; ni++) {
                    mma_tf32(acc[mi][ni], aHf[mi], bHf[ni]);
                    mma_tf32(acc[mi][ni], aHf[mi], bLf[ni]);
                    mma_tf32(acc[mi][ni], aLf[mi], bHf[ni]);
                }
        }
        if (more) {
            __syncthreads();
            storeS();
            __syncthreads();
        }
    }

#pragma unroll
    for (int mi = 0; mi < 2; mi++) {
        int r0 = row0 + m0 + mi * 16 + gq;
#pragma unroll
        for (int ni = 0; ni < 4; ni++) {
            int c = col0 + n0 + ni * 8 + tg * 2;
            if (c < Kn) {
                if (r0 < M) {
                    float2 v = make_float2(acc[mi][ni][0], acc[mi][ni][1]);
                    *(float2*)(g_feat + (size_t)r0 * Kn + c) = v;
                }
                if (r0 + 8 < M) {
                    float2 v = make_float2(acc[mi][ni][2], acc[mi][ni][3]);
                    *(float2*)(g_feat + (size_t)(r0 + 8) * Kn + c) = v;
                }
            }
        }
    }
}

// ---------------- per-node attention projections (el, er) -------------------
__global__ void elr_kernel(const float* __restrict__ al,
                           const float* __restrict__ ar,
                           int F) {
    int w = (blockIdx.x * blockDim.x + threadIdx.x) >> 5;
    int lane = threadIdx.x & 31;
    if (w >= NN) return;
    const float* frow = g_feat + (size_t)w * HH * F;
#pragma unroll
    for (int h = 0; h < HH; h++) {
        float sl = 0.f, sr = 0.f;
        for (int d = lane; d < F; d += 32) {
            float f = frow[h * F + d];
            sl = fmaf(f, al[h * F + d], sl);
            sr = fmaf(f, ar[h * F + d], sr);
        }
        sl = warpsum(sl);
        sr = warpsum(sr);
        if (lane == 0) {
            g_el[w * HH + h] = sl;
            g_er[w * HH + h] = sr;
        }
    }
}

// ---------------- fused softmax + aggregation, layers 1/2 (HF=128) ----------
// One warp per dst node; register-cached exps (deg <= 128); gather loop
// manually unrolled x4 with independent accumulators for MLP.
#define NCH 4
__global__ void aggr128_kernel(const float* __restrict__ bias) {
    int node = (blockIdx.x * blockDim.x + threadIdx.x) >> 5;
    int lane = threadIdx.x & 31;
    if (node >= NN) return;
    int beg = g_off[node], end = g_off[node + 1];
    int deg = end - beg;
    float4 er4 = *(const float4*)(g_er + (size_t)node * 4);

    int   sc[NCH];
    float x0c[NCH], x1c[NCH], x2c[NCH], x3c[NCH];
    float d0 = 0.f, d1 = 0.f, d2 = 0.f, d3 = 0.f;
    int nch = (deg + 31) >> 5; if (nch > NCH) nch = NCH;

#pragma unroll
    for (int c = 0; c < NCH; c++) {
        sc[c] = 0; x0c[c] = 0.f; x1c[c] = 0.f; x2c[c] = 0.f; x3c[c] = 0.f;
        if (c < nch) {
            int p = beg + c * 32 + lane;
            if (p < end) {
                int s = g_esrc[p]; sc[c] = s;
                float4 el4 = *(const float4*)(g_el + (size_t)s * 4);
                float e0 = __expf(lrelu(el4.x + er4.x));
                float e1 = __expf(lrelu(el4.y + er4.y));
                float e2 = __expf(lrelu(el4.z + er4.z));
                float e3 = __expf(lrelu(el4.w + er4.w));
                x0c[c] = e0; x1c[c] = e1; x2c[c] = e2; x3c[c] = e3;
                d0 += e0; d1 += e1; d2 += e2; d3 += e3;
            }
        }
    }
    for (int p = beg + NCH * 32 + lane; p < end; p += 32) {
        int s = g_esrc[p];
        float4 el4 = *(const float4*)(g_el + (size_t)s * 4);
        d0 += __expf(lrelu(el4.x + er4.x));
        d1 += __expf(lrelu(el4.y + er4.y));
        d2 += __expf(lrelu(el4.z + er4.z));
        d3 += __expf(lrelu(el4.w + er4.w));
    }
    d0 = warpsum(d0); d1 = warpsum(d1); d2 = warpsum(d2); d3 = warpsum(d3);
    float i0 = 1.f / d0, i1 = 1.f / d1, i2 = 1.f / d2, i3 = 1.f / d3;
#pragma unroll
    for (int c = 0; c < NCH; c++) {
        x0c[c] *= i0; x1c[c] *= i1; x2c[c] *= i2; x3c[c] *= i3;
    }

    int h = lane >> 3;
    const float* fb = g_feat + (size_t)lane * 4;
    float4 A0 = make_float4(0.f, 0.f, 0.f, 0.f), A1 = A0, A2 = A0, A3 = A0;
#pragma unroll
    for (int c = 0; c < NCH; c++) {
        if (c < nch) {
            int cnt = min(32, deg - c * 32);
            int j = 0;
            // 4-edge unroll: batch shuffles, 4 independent LDG.128 in flight
            for (; j + 4 <= cnt; j += 4) {
                int s0 = __shfl_sync(FULLMASK, sc[c], j);
                int s1 = __shfl_sync(FULLMASK, sc[c], j + 1);
                int s2 = __shfl_sync(FULLMASK, sc[c], j + 2);
                int s3 = __shfl_sync(FULLMASK, sc[c], j + 3);
                float w00 = __shfl_sync(FULLMASK, x0c[c], j);
                float w01 = __shfl_sync(FULLMASK, x1c[c], j);
                float w02 = __shfl_sync(FULLMASK, x2c[c], j);
                float w03 = __shfl_sync(FULLMASK, x3c[c], j);
                float w10 = __shfl_sync(FULLMASK, x0c[c], j + 1);
                float w11 = __shfl_sync(FULLMASK, x1c[c], j + 1);
                float w12 = __shfl_sync(FULLMASK, x2c[c], j + 1);
                float w13 = __shfl_sync(FULLMASK, x3c[c], j + 1);
                float w20 = __shfl_sync(FULLMASK, x0c[c], j + 2);
                float w21 = __shfl_sync(FULLMASK, x1c[c], j + 2);
                float w22 = __shfl_sync(FULLMASK, x2c[c], j + 2);
                float w23 = __shfl_sync(FULLMASK, x3c[c], j + 2);
                float w30 = __shfl_sync(FULLMASK, x0c[c], j + 3);
                float w31 = __shfl_sync(FULLMASK, x1c[c], j + 3);
                float w32 = __shfl_sync(FULLMASK, x2c[c], j + 3);
                float w33 = __shfl_sync(FULLMASK, x3c[c], j + 3);
                float4 f0 = *(const float4*)(fb + (size_t)s0 * HD);
                float4 f1 = *(const float4*)(fb + (size_t)s1 * HD);
                float4 f2 = *(const float4*)(fb + (size_t)s2 * HD);
                float4 f3 = *(const float4*)(fb + (size_t)s3 * HD);
                float a0 = h == 0 ? w00 : (h == 1 ? w01 : (h == 2 ? w02 : w03));
                float a1 = h == 0 ? w10 : (h == 1 ? w11 : (h == 2 ? w12 : w13));
                float a2 = h == 0 ? w20 : (h == 1 ? w21 : (h == 2 ? w22 : w23));
                float a3 = h == 0 ? w30 : (h == 1 ? w31 : (h == 2 ? w32 : w33));
                A0.x = fmaf(a0, f0.x, A0.x); A0.y = fmaf(a0, f0.y, A0.y);
                A0.z = fmaf(a0, f0.z, A0.z); A0.w = fmaf(a0, f0.w, A0.w);
                A1.x = fmaf(a1, f1.x, A1.x); A1.y = fmaf(a1, f1.y, A1.y);
                A1.z = fmaf(a1, f1.z, A1.z); A1.w = fmaf(a1, f1.w, A1.w);
                A2.x = fmaf(a2, f2.x, A2.x); A2.y = fmaf(a2, f2.y, A2.y);
                A2.z = fmaf(a2, f2.z, A2.z); A2.w = fmaf(a2, f2.w, A2.w);
                A3.x = fmaf(a3, f3.x, A3.x); A3.y = fmaf(a3, f3.y, A3.y);
                A3.z = fmaf(a3, f3.z, A3.z); A3.w = fmaf(a3, f3.w, A3.w);
            }
            for (; j < cnt; j++) {
                int sj = __shfl_sync(FULLMASK, sc[c], j);
                float w0 = __shfl_sync(FULLMASK, x0c[c], j);
                float w1 = __shfl_sync(FULLMASK, x1c[c], j);
                float w2 = __shfl_sync(FULLMASK, x2c[c], j);
                float w3 = __shfl_sync(FULLMASK, x3c[c], j);
                float a = h == 0 ? w0 : (h == 1 ? w1 : (h == 2 ? w2 : w3));
                float4 f = *(const float4*)(fb + (size_t)sj * HD);
                A0.x = fmaf(a, f.x, A0.x); A0.y = fmaf(a, f.y, A0.y);
                A0.z = fmaf(a, f.z, A0.z); A0.w = fmaf(a, f.w, A0.w);
            }
        }
    }
    // tail: deg > 128 (rare) — recompute alphas
    for (int base = beg + NCH * 32; base < end; base += 32) {
        int p = base + lane;
        int cnt = min(32, end - base);
        int s = 0; float x0 = 0.f, x1 = 0.f, x2 = 0.f, x3 = 0.f;
        if (p < end) {
            s = g_esrc[p];
            float4 el4 = *(const float4*)(g_el + (size_t)s * 4);
            x0 = __expf(lrelu(el4.x + er4.x)) * i0;
            x1 = __expf(lrelu(el4.y + er4.y)) * i1;
            x2 = __expf(lrelu(el4.z + er4.z)) * i2;
            x3 = __expf(lrelu(el4.w + er4.w)) * i3;
        }
        for (int q = 0; q < cnt; q++) {
            int sj = __shfl_sync(FULLMASK, s, q);
            float w0 = __shfl_sync(FULLMASK, x0, q);
            float w1 = __shfl_sync(FULLMASK, x1, q);
            float w2 = __shfl_sync(FULLMASK, x2, q);
            float w3 = __shfl_sync(FULLMASK, x3, q);
            float a = h == 0 ? w0 : (h == 1 ? w1 : (h == 2 ? w2 : w3));
            float4 f = *(const float4*)(fb + (size_t)sj * HD);
            A0.x = fmaf(a, f.x, A0.x); A0.y = fmaf(a, f.y, A0.y);
            A0.z = fmaf(a, f.z, A0.z); A0.w = fmaf(a, f.w, A0.w);
        }
    }

    float4 acc;
    acc.x = (A0.x + A1.x) + (A2.x + A3.x);
    acc.y = (A0.y + A1.y) + (A2.y + A3.y);
    acc.z = (A0.z + A1.z) + (A2.z + A3.z);
    acc.w = (A0.w + A1.w) + (A2.w + A3.w);
    float4 bv = *(const float4*)(bias + lane * 4);
    float4 o;
    o.x = fmaxf(acc.x + bv.x, 0.f);
    o.y = fmaxf(acc.y + bv.y, 0.f);
    o.z = fmaxf(acc.z + bv.z, 0.f);
    o.w = fmaxf(acc.w + bv.w, 0.f);
    *(float4*)(g_hbuf + (size_t)node * HD + lane * 4) = o;
}

// ---------------- fused softmax + aggr + head-mean + log_softmax, layer 3 ---
__global__ void aggr47_final_kernel(const float* __restrict__ b3,
                                    float* __restrict__ out) {
    int node = (blockIdx.x * blockDim.x + threadIdx.x) >> 5;
    int lane = threadIdx.x & 31;
    if (node >= NN) return;
    int beg = g_off[node], end = g_off[node + 1];
    int deg = end - beg;
    float4 er4 = *(const float4*)(g_er + (size_t)node * 4);

    int   sc[NCH];
    float x0c[NCH], x1c[NCH], x2c[NCH], x3c[NCH];
    float d0 = 0.f, d1 = 0.f, d2 = 0.f, d3 = 0.f;
    int nch = (deg + 31) >> 5; if (nch > NCH) nch = NCH;

#pragma unroll
    for (int c = 0; c < NCH; c++) {
        sc[c] = 0; x0c[c] = 0.f; x1c[c] = 0.f; x2c[c] = 0.f; x3c[c] = 0.f;
        if (c < nch) {
            int p = beg + c * 32 + lane;
            if (p < end) {
                int s = g_esrc[p]; sc[c] = s;
                float4 el4 = *(const float4*)(g_el + (size_t)s * 4);
                float e0 = __expf(lrelu(el4.x + er4.x));
                float e1 = __expf(lrelu(el4.y + er4.y));
                float e2 = __expf(lrelu(el4.z + er4.z));
                float e3 = __expf(lrelu(el4.w + er4.w));
                x0c[c] = e0; x1c[c] = e1; x2c[c] = e2; x3c[c] = e3;
                d0 += e0; d1 += e1; d2 += e2; d3 += e3;
            }
        }
    }
    for (int p = beg + NCH * 32 + lane; p < end; p += 32) {
        int s = g_esrc[p];
        float4 el4 = *(const float4*)(g_el + (size_t)s * 4);
        d0 += __expf(lrelu(el4.x + er4.x));
        d1 += __expf(lrelu(el4.y + er4.y));
        d2 += __expf(lrelu(el4.z + er4.z));
        d3 += __expf(lrelu(el4.w + er4.w));
    }
    d0 = warpsum(d0); d1 = warpsum(d1); d2 = warpsum(d2); d3 = warpsum(d3);
    float i0 = 1.f / d0, i1 = 1.f / d1, i2 = 1.f / d2, i3 = 1.f / d3;
#pragma unroll
    for (int c = 0; c < NCH; c++) {
        x0c[c] *= i0; x1c[c] *= i1; x2c[c] *= i2; x3c[c] *= i3;
    }

    bool hi = (lane < CC - 32);
    int cx = 32 + lane;
    float a0A = 0.f, a0B = 0.f, a1A = 0.f, a1B = 0.f;
#pragma unroll
    for (int c = 0; c < NCH; c++) {
        if (c < nch) {
            int cnt = min(32, deg - c * 32);
            int j = 0;
            // 2-edge unroll: 16 scalar loads in flight
            for (; j + 2 <= cnt; j += 2) {
                int s0 = __shfl_sync(FULLMASK, sc[c], j);
                int s1 = __shfl_sync(FULLMASK, sc[c], j + 1);
                float w00 = __shfl_sync(FULLMASK, x0c[c], j);
                float w01 = __shfl_sync(FULLMASK, x1c[c], j);
                float w02 = __shfl_sync(FULLMASK, x2c[c], j);
                float w03 = __shfl_sync(FULLMASK, x3c[c], j);
                float w10 = __shfl_sync(FULLMASK, x0c[c], j + 1);
                float w11 = __shfl_sync(FULLMASK, x1c[c], j + 1);
                float w12 = __shfl_sync(FULLMASK, x2c[c], j + 1);
                float w13 = __shfl_sync(FULLMASK, x3c[c], j + 1);
                const float* fr0 = g_feat + (size_t)s0 * HC;
                const float* fr1 = g_feat + (size_t)s1 * HC;
                a0A += w00 * fr0[lane] + w01 * fr0[CC + lane]
                     + w02 * fr0[2 * CC + lane] + w03 * fr0[3 * CC + lane];
                a0B += w10 * fr1[lane] + w11 * fr1[CC + lane]
                     + w12 * fr1[2 * CC + lane] + w13 * fr1[3 * CC + lane];
                if (hi) {
                    a1A += w00 * fr0[cx] + w01 * fr0[CC + cx]
                         + w02 * fr0[2 * CC + cx] + w03 * fr0[3 * CC + cx];
                    a1B += w10 * fr1[cx] + w11 * fr1[CC + cx]
                         + w12 * fr1[2 * CC + cx] + w13 * fr1[3 * CC + cx];
                }
            }
            for (; j < cnt; j++) {
                int sj = __shfl_sync(FULLMASK, sc[c], j);
                float w0 = __shfl_sync(FULLMASK, x0c[c], j);
                float w1 = __shfl_sync(FULLMASK, x1c[c], j);
                float w2 = __shfl_sync(FULLMASK, x2c[c], j);
                float w3 = __shfl_sync(FULLMASK, x3c[c], j);
                const float* fr = g_feat + (size_t)sj * HC;
                a0A += w0 * fr[lane] + w1 * fr[CC + lane]
                     + w2 * fr[2 * CC + lane] + w3 * fr[3 * CC + lane];
                if (hi)
                    a1A += w0 * fr[cx] + w1 * fr[CC + cx]
                         + w2 * fr[2 * CC + cx] + w3 * fr[3 * CC + cx];
            }
        }
    }
    for (int base = beg + NCH * 32; base < end; base += 32) {
        int p = base + lane;
        int cnt = min(32, end - base);
        int s = 0; float x0 = 0.f, x1 = 0.f, x2 = 0.f, x3 = 0.f;
        if (p < end) {
            s = g_esrc[p];
            float4 el4 = *(const float4*)(g_el + (size_t)s * 4);
            x0 = __expf(lrelu(el4.x + er4.x)) * i0;
            x1 = __expf(lrelu(el4.y + er4.y)) * i1;
            x2 = __expf(lrelu(el4.z + er4.z)) * i2;
            x3 = __expf(lrelu(el4.w + er4.w)) * i3;
        }
        for (int q = 0; q < cnt; q++) {
            int sj = __shfl_sync(FULLMASK, s, q);
            float w0 = __shfl_sync(FULLMASK, x0, q);
            float w1 = __shfl_sync(FULLMASK, x1, q);
            float w2 = __shfl_sync(FULLMASK, x2, q);
            float w3 = __shfl_sync(FULLMASK, x3, q);
            const float* fr = g_feat + (size_t)sj * HC;
            a0A += w0 * fr[lane] + w1 * fr[CC + lane]
                 + w2 * fr[2 * CC + lane] + w3 * fr[3 * CC + lane];
            if (hi)
                a1A += w0 * fr[cx] + w1 * fr[CC + cx]
                     + w2 * fr[2 * CC + cx] + w3 * fr[3 * CC + cx];
        }
    }

    float a0 = a0A + a0B, a1 = a1A + a1B;
    float v0 = a0 * 0.25f + 0.25f * (b3[lane] + b3[CC + lane] +
                                     b3[2 * CC + lane] + b3[3 * CC + lane]);
    float v1 = 0.f;
    if (hi)
        v1 = a1 * 0.25f + 0.25f * (b3[cx] + b3[CC + cx] +
                                   b3[2 * CC + cx] + b3[3 * CC + cx]);
    float mm = v0;
    if (hi) mm = fmaxf(mm, v1);
    mm = warpmax(mm);
    float s = __expf(v0 - mm);
    if (hi) s += __expf(v1 - mm);
    s = warpsum(s);
    float lse = logf(s) + mm;
    out[(size_t)node * CC + lane] = v0 - lse;
    if (hi) out[(size_t)node * CC + cx] = v1 - lse;
}

// ---------------- host orchestration ----------------------------------------
extern "C" void kernel_launch(void* const* d_in, const int* in_sizes, int n_in,
                              void* d_out, int out_size) {
    const float* x   = (const float*)d_in[0];
    const int*   src = (const int*)  d_in[1];
    const int*   dst = (const int*)  d_in[2];
    const float* W1  = (const float*)d_in[3];
    const float* al1 = (const float*)d_in[4];
    const float* ar1 = (const float*)d_in[5];
    const float* b1  = (const float*)d_in[6];
    const float* W2  = (const float*)d_in[7];
    const float* al2 = (const float*)d_in[8];
    const float* ar2 = (const float*)d_in[9];
    const float* b2  = (const float*)d_in[10];
    const float* W3  = (const float*)d_in[11];
    const float* al3 = (const float*)d_in[12];
    const float* ar3 = (const float*)d_in[13];
    const float* b3  = (const float*)d_in[14];
    float* out = (float*)d_out;

    // ---- CSR build (same graph for all 3 layers) ----
    zero_deg_kernel<<<(NN + 255) / 256, 256>>>();
    hist_kernel<<<(EE + 255) / 256, 256>>>(dst);
    scan_kernel<<<1, 1024>>>();
    scatter_kernel<<<(EE + 255) / 256, 256>>>(src, dst);

    int node_warp_blocks = (NN * 32 + 255) / 256;
    int mblocks = (NN + GBM - 1) / GBM;

    // ---- Layer 1: IN -> H*D, ReLU ----
    tf32_gemm_kernel<<<dim3(2, mblocks), 256>>>(x, W1, NN, IN_F, HD, 0);
    elr_kernel<<<node_warp_blocks, 256>>>(al1, ar1, DD);
    aggr128_kernel<<<node_warp_blocks, 256>>>(b1);

    // ---- Layer 2: H*D -> H*D, ReLU ----
    tf32_gemm_kernel<<<dim3(2, mblocks), 256>>>(nullptr, W2, NN, HD, HD, 1);
    elr_kernel<<<node_warp_blocks, 256>>>(al2, ar2, DD);
    aggr128_kernel<<<node_warp_blocks, 256>>>(b2);

    // ---- Layer 3: H*D -> H*C, head-mean + log_softmax ----
    tf32_gemm_kernel<<<dim3(3, mblocks), 256>>>(nullptr, W3, NN, HD, HC, 1);
    elr_kernel<<<node_warp_blocks, 256>>>(al3, ar3, CC);
    aggr47_final_kernel<<<node_warp_blocks, 256>>>(b3, out);
}

// round 11
// speedup vs baseline: 1.4723x; 1.2508x over previous
#include <cuda_runtime.h>
#include <math.h>
#include <float.h>

#define NN 100000
#define EE 1600000
#define IN_F 256
#define HH 4
#define DD 32
#define CC 47
#define HD 128        // H*D
#define HC 188        // H*C
#define NEG_SLOPE 0.2f
#define FULLMASK 0xffffffffu

// ---------------- scratch (static device globals; no allocation) ------------
__device__ __align__(16) float g_feat[(size_t)NN * HC];
__device__ __align__(16) float g_hbuf[(size_t)NN * HD];
__device__ __align__(16) float g_el[NN * HH];
__device__ __align__(16) float g_er[NN * HH];
__device__ int g_deg[NN];
__device__ int g_off[NN + 1];
__device__ int g_cur[NN];
__device__ int g_esrc[EE];
// CSR single-kernel infrastructure
__device__ unsigned g_barcnt[8];      // monotonic barrier counters (zero-init)
__device__ int g_chunksum[512];
__device__ int g_chunkoff[512];

// ---------------- warp helpers ----------------------------------------------
__device__ __forceinline__ float warpsum(float v) {
#pragma unroll
    for (int o = 16; o; o >>= 1) v += __shfl_xor_sync(FULLMASK, v, o);
    return v;
}
__device__ __forceinline__ float warpmax(float v) {
#pragma unroll
    for (int o = 16; o; o >>= 1) v = fmaxf(v, __shfl_xor_sync(FULLMASK, v, o));
    return v;
}
__device__ __forceinline__ float lrelu(float v) {
    return v > 0.f ? v : NEG_SLOPE * v;
}
__device__ __forceinline__ unsigned f2tf(float x) {
    unsigned r;
    asm("cvt.rna.tf32.f32 %0, %1;" : "=r"(r) : "f"(x));
    return r;
}

// ---------------- single-kernel CSR build ------------------------------------
// grid = CSRB blocks x 256 threads, guaranteed co-resident (4 blocks/SM).
// Software grid barrier: monotonic counter, release-fence before arrive,
// volatile (L1-bypassing) polls with nanosleep backoff. Cross-block reads
// after a barrier use __ldcg (L1 is not coherent w.r.t. other blocks' stores).
#define CSRB 592
#define CSRT 256

__device__ __forceinline__ void grid_barrier(int slot) {
    __threadfence();
    __syncthreads();
    if (threadIdx.x == 0) {
        unsigned ticket = atomicAdd(&g_barcnt[slot], 1u) + 1u;
        unsigned tgt = ((ticket + CSRB - 1u) / CSRB) * CSRB;
        while (*((volatile unsigned*)&g_barcnt[slot]) < tgt) __nanosleep(64);
    }
    __syncthreads();
}

__global__ void __launch_bounds__(CSRT)
csr_build_kernel(const int* __restrict__ src, const int* __restrict__ dst) {
    __shared__ int ws[8];
    __shared__ int carry_s;
    int tid = threadIdx.x, bid = blockIdx.x;
    int gtid = bid * CSRT + tid;
    const int gstride = CSRB * CSRT;
    const int NCHUNK = (NN + CSRT - 1) / CSRT;   // 391
    int lane = tid & 31, wid = tid >> 5;

    // phase 0: zero degrees
    for (int i = gtid; i < NN; i += gstride) g_deg[i] = 0;
    grid_barrier(0);

    // phase 1: histogram
    for (int e = gtid; e < EE; e += gstride) atomicAdd(&g_deg[dst[e]], 1);
    grid_barrier(1);

    // phase 2: per-chunk exclusive scan (chunk = 256 nodes, one block each)
    if (bid < NCHUNK) {
        int i = bid * CSRT + tid;
        int v = (i < NN) ? __ldcg(&g_deg[i]) : 0;
        int x = v;
#pragma unroll
        for (int o = 1; o < 32; o <<= 1) {
            int t = __shfl_up_sync(FULLMASK, x, o);
            if (lane >= o) x += t;
        }
        if (lane == 31) ws[wid] = x;
        __syncthreads();
        if (wid == 0 && lane < 8) {
            int w = ws[lane];
#pragma unroll
            for (int o = 1; o < 8; o <<= 1) {
                int t = __shfl_up_sync(0xffu, w, o);
                if (lane >= o) w += t;
            }
            ws[lane] = w;
        }
        __syncthreads();
        int woff = wid ? ws[wid - 1] : 0;
        int incl = x + woff;
        if (i < NN) g_off[i] = incl - v;           // chunk-local exclusive
        if (tid == CSRT - 1) g_chunksum[bid] = incl;
    }
    grid_barrier(2);

    // phase 3: block 0 scans chunk totals -> g_chunkoff (exclusive) + total
    if (bid == 0) {
        if (tid == 0) carry_s = 0;
        __syncthreads();
        for (int base = 0; base < NCHUNK; base += CSRT) {
            int i = base + tid;
            int v = (i < NCHUNK) ? __ldcg(&g_chunksum[i]) : 0;
            int x = v;
#pragma unroll
            for (int o = 1; o < 32; o <<= 1) {
                int t = __shfl_up_sync(FULLMASK, x, o);
                if (lane >= o) x += t;
            }
            if (lane == 31) ws[wid] = x;
            __syncthreads();
            if (wid == 0 && lane < 8) {
                int w = ws[lane];
#pragma unroll
                for (int o = 1; o < 8; o <<= 1) {
                    int t = __shfl_up_sync(0xffu, w, o);
                    if (lane >= o) w += t;
                }
                ws[lane] = w;
            }
            __syncthreads();
            int woff = wid ? ws[wid - 1] : 0;
            int incl = x + woff;
            int carry = carry_s;
            if (i < NCHUNK) g_chunkoff[i] = carry + incl - v;
            __syncthreads();
            if (tid == CSRT - 1) carry_s = carry + incl;
            __syncthreads();
        }
        if (tid == 0) g_off[NN] = carry_s;
    }
    grid_barrier(3);

    // phase 4: add chunk offsets, init cursors
    if (bid < NCHUNK) {
        int i = bid * CSRT + tid;
        if (i < NN) {
            int off = __ldcg(&g_chunkoff[bid]);
            int e = g_off[i] + off;   // own block's phase-2 store: coherent
            g_off[i] = e;
            g_cur[i] = e;
        }
    }
    grid_barrier(4);

    // phase 5: scatter src ids into dst-grouped buckets
    for (int e = gtid; e < EE; e += gstride) {
        int p = atomicAdd(&g_cur[dst[e]], 1);
        g_esrc[p] = src[e];
    }
}

// ---------------- 3xTF32 tensor-core GEMM -----------------------------------
#define GBM 128
#define GBN 64
#define GBK 16
#define ASTR (GBM + 8)
#define BSTR (GBN + 8)

__device__ __forceinline__ void mma_tf32(float* c, const unsigned* a, const unsigned* b) {
    asm("mma.sync.aligned.m16n8k8.row.col.f32.tf32.tf32.f32 "
        "{%0,%1,%2,%3}, {%4,%5,%6,%7}, {%8,%9}, {%0,%1,%2,%3};"
        : "+f"(c[0]), "+f"(c[1]), "+f"(c[2]), "+f"(c[3])
        : "r"(a[0]), "r"(a[1]), "r"(a[2]), "r"(a[3]), "r"(b[0]), "r"(b[1]));
}

__global__ void __launch_bounds__(256, 2)
tf32_gemm_kernel(const float* __restrict__ Aext,
                 const float* __restrict__ B,
                 int M, int K, int Kn, int use_hbuf) {
    __shared__ unsigned Ah[GBK][ASTR], Al[GBK][ASTR];
    __shared__ unsigned Bh[GBK][BSTR], Bl[GBK][BSTR];

    const float* __restrict__ A = use_hbuf ? (const float*)g_hbuf : Aext;

    int tid = threadIdx.x;
    int wid = tid >> 5, lane = tid & 31;
    int row0 = blockIdx.y * GBM, col0 = blockIdx.x * GBN;
    int m0 = (wid >> 1) * 32;
    int n0 = (wid & 1) * 32;
    int gq = lane >> 2;
    int tg = lane & 3;

    int a_m = tid >> 1;
    int a_k = (tid & 1) * 8;
    int b_k = tid >> 4;
    int b_n = (tid & 15) * 4;

    float aS[8];
    float bS[4];

    auto loadG = [&](int k0) {
        int row = row0 + a_m;
        if (row < M) {
            const float* ap = A + (size_t)row * K + k0 + a_k;
            float4 v0 = *(const float4*)(ap);
            float4 v1 = *(const float4*)(ap + 4);
            aS[0] = v0.x; aS[1] = v0.y; aS[2] = v0.z; aS[3] = v0.w;
            aS[4] = v1.x; aS[5] = v1.y; aS[6] = v1.z; aS[7] = v1.w;
        } else {
#pragma unroll
            for (int j = 0; j < 8; j++) aS[j] = 0.f;
        }
        int col = col0 + b_n;
        const float* bp = B + (size_t)(k0 + b_k) * Kn;
        if (col + 3 < Kn) {
            float4 v = *(const float4*)(bp + col);
            bS[0] = v.x; bS[1] = v.y; bS[2] = v.z; bS[3] = v.w;
        } else {
#pragma unroll
            for (int j = 0; j < 4; j++) bS[j] = (col + j < Kn) ? bp[col + j] : 0.f;
        }
    };
    auto storeS = [&]() {
#pragma unroll
        for (int j = 0; j < 8; j++) {
            unsigned h = f2tf(aS[j]);
            Ah[a_k + j][a_m] = h;
            Al[a_k + j][a_m] = f2tf(aS[j] - __uint_as_float(h));
        }
#pragma unroll
        for (int j = 0; j < 4; j++) {
            unsigned h = f2tf(bS[j]);
            Bh[b_k][b_n + j] = h;
            Bl[b_k][b_n + j] = f2tf(bS[j] - __uint_as_float(h));
        }
    };

    float acc[2][4][4];
#pragma unroll
    for (int mi = 0; mi < 2; mi++)
#pragma unroll
        for (int ni = 0; ni < 4; ni++)
#pragma unroll
            for (int r = 0; r < 4; r++) acc[mi][ni][r] = 0.f;

    loadG(0);
    storeS();
    __syncthreads();

    for (int k0 = 0; k0 < K; k0 += GBK) {
        bool more = (k0 + GBK < K);
        if (more) loadG(k0 + GBK);
#pragma unroll
        for (int kk = 0; kk < GBK; kk += 8) {
            unsigned aHf[2][4], aLf[2][4];
#pragma unroll
            for (int mi = 0; mi < 2; mi++) {
                int mr = m0 + mi * 16 + gq;
                aHf[mi][0] = Ah[kk + tg][mr];
                aHf[mi][1] = Ah[kk + tg][mr + 8];
                aHf[mi][2] = Ah[kk + 4 + tg][mr];
                aHf[mi][3] = Ah[kk + 4 + tg][mr + 8];
                aLf[mi][0] = Al[kk + tg][mr];
                aLf[mi][1] = Al[kk + tg][mr + 8];
                aLf[mi][2] = Al[kk + 4 + tg][mr];
                aLf[mi][3] = Al[kk + 4 + tg][mr + 8];
            }
            unsigned bHf[4][2], bLf[4][2];
#pragma unroll
            for (int ni = 0; ni < 4; ni++) {
                int bc = n0 + ni * 8 + gq;
                bHf[ni][0] = Bh[kk + tg][bc];
                bHf[ni][1] = Bh[kk + 4 + tg][bc];
                bLf[ni][0] = Bl[kk + tg][bc];
                bLf[ni][1] = Bl[kk + 4 + tg][bc];
            }
#pragma unroll
            for (int mi = 0; mi < 2; mi++)
#pragma unroll
                for (int ni = 0; ni < 4; ni++) {
                    mma_tf32(acc[mi][ni], aHf[mi], bHf[ni]);
                    mma_tf32(acc[mi][ni], aHf[mi], bLf[ni]);
                    mma_tf32(acc[mi][ni], aLf[mi], bHf[ni]);
                }
        }
        if (more) {
            __syncthreads();
            storeS();
            __syncthreads();
        }
    }

#pragma unroll
    for (int mi = 0; mi < 2; mi++) {
        int r0 = row0 + m0 + mi * 16 + gq;
#pragma unroll
        for (int ni = 0; ni < 4; ni++) {
            int c = col0 + n0 + ni * 8 + tg * 2;
            if (c < Kn) {
                if (r0 < M) {
                    float2 v = make_float2(acc[mi][ni][0], acc[mi][ni][1]);
                    *(float2*)(g_feat + (size_t)r0 * Kn + c) = v;
                }
                if (r0 + 8 < M) {
                    float2 v = make_float2(acc[mi][ni][2], acc[mi][ni][3]);
                    *(float2*)(g_feat + (size_t)(r0 + 8) * Kn + c) = v;
                }
            }
        }
    }
}

// ---------------- per-node attention projections (el, er), v2 ---------------
// warp per node; lane l -> head h = l>>3, 8 lanes per head; 6 shfl per node.
__global__ void elr_kernel(const float* __restrict__ al,
                           const float* __restrict__ ar,
                           int F) {
    int w = (blockIdx.x * blockDim.x + threadIdx.x) >> 5;
    int lane = threadIdx.x & 31;
    if (w >= NN) return;
    int h = lane >> 3, j = lane & 7;
    const float* frow = g_feat + (size_t)w * HH * F + h * F;
    const float* alh = al + h * F;
    const float* arh = ar + h * F;
    float sl = 0.f, sr = 0.f;
    for (int d = j; d < F; d += 8) {
        float f = frow[d];
        sl = fmaf(f, alh[d], sl);
        sr = fmaf(f, arh[d], sr);
    }
#pragma unroll
    for (int o = 4; o; o >>= 1) {
        sl += __shfl_xor_sync(FULLMASK, sl, o);
        sr += __shfl_xor_sync(FULLMASK, sr, o);
    }
    if (j == 0) {
        g_el[w * HH + h] = sl;
        g_er[w * HH + h] = sr;
    }
}

// ---------------- fused softmax + aggregation, layers 1/2 (R7 version) ------
#define NCH 4
__global__ void aggr128_kernel(const float* __restrict__ bias) {
    int node = (blockIdx.x * blockDim.x + threadIdx.x) >> 5;
    int lane = threadIdx.x & 31;
    if (node >= NN) return;
    int beg = g_off[node], end = g_off[node + 1];
    int deg = end - beg;
    float4 er4 = *(const float4*)(g_er + (size_t)node * 4);

    int   sc[NCH];
    float x0c[NCH], x1c[NCH], x2c[NCH], x3c[NCH];
    float d0 = 0.f, d1 = 0.f, d2 = 0.f, d3 = 0.f;
    int nch = (deg + 31) >> 5; if (nch > NCH) nch = NCH;

#pragma unroll
    for (int c = 0; c < NCH; c++) {
        sc[c] = 0; x0c[c] = 0.f; x1c[c] = 0.f; x2c[c] = 0.f; x3c[c] = 0.f;
        if (c < nch) {
            int p = beg + c * 32 + lane;
            if (p < end) {
                int s = g_esrc[p]; sc[c] = s;
                float4 el4 = *(const float4*)(g_el + (size_t)s * 4);
                float e0 = __expf(lrelu(el4.x + er4.x));
                float e1 = __expf(lrelu(el4.y + er4.y));
                float e2 = __expf(lrelu(el4.z + er4.z));
                float e3 = __expf(lrelu(el4.w + er4.w));
                x0c[c] = e0; x1c[c] = e1; x2c[c] = e2; x3c[c] = e3;
                d0 += e0; d1 += e1; d2 += e2; d3 += e3;
            }
        }
    }
    for (int p = beg + NCH * 32 + lane; p < end; p += 32) {
        int s = g_esrc[p];
        float4 el4 = *(const float4*)(g_el + (size_t)s * 4);
        d0 += __expf(lrelu(el4.x + er4.x));
        d1 += __expf(lrelu(el4.y + er4.y));
        d2 += __expf(lrelu(el4.z + er4.z));
        d3 += __expf(lrelu(el4.w + er4.w));
    }
    d0 = warpsum(d0); d1 = warpsum(d1); d2 = warpsum(d2); d3 = warpsum(d3);
    float i0 = 1.f / d0, i1 = 1.f / d1, i2 = 1.f / d2, i3 = 1.f / d3;
#pragma unroll
    for (int c = 0; c < NCH; c++) {
        x0c[c] *= i0; x1c[c] *= i1; x2c[c] *= i2; x3c[c] *= i3;
    }

    int h = lane >> 3;
    float4 acc = make_float4(0.f, 0.f, 0.f, 0.f);
#pragma unroll
    for (int c = 0; c < NCH; c++) {
        if (c < nch) {
            int cnt = min(32, deg - c * 32);
            for (int j = 0; j < cnt; j++) {
                int sj = __shfl_sync(FULLMASK, sc[c], j);
                float w0 = __shfl_sync(FULLMASK, x0c[c], j);
                float w1 = __shfl_sync(FULLMASK, x1c[c], j);
                float w2 = __shfl_sync(FULLMASK, x2c[c], j);
                float w3 = __shfl_sync(FULLMASK, x3c[c], j);
                float w = h == 0 ? w0 : (h == 1 ? w1 : (h == 2 ? w2 : w3));
                float4 f = *(const float4*)(g_feat + (size_t)sj * HD + lane * 4);
                acc.x = fmaf(w, f.x, acc.x);
                acc.y = fmaf(w, f.y, acc.y);
                acc.z = fmaf(w, f.z, acc.z);
                acc.w = fmaf(w, f.w, acc.w);
            }
        }
    }
    for (int base = beg + NCH * 32; base < end; base += 32) {
        int p = base + lane;
        int cnt = min(32, end - base);
        int s = 0; float x0 = 0.f, x1 = 0.f, x2 = 0.f, x3 = 0.f;
        if (p < end) {
            s = g_esrc[p];
            float4 el4 = *(const float4*)(g_el + (size_t)s * 4);
            x0 = __expf(lrelu(el4.x + er4.x)) * i0;
            x1 = __expf(lrelu(el4.y + er4.y)) * i1;
            x2 = __expf(lrelu(el4.z + er4.z)) * i2;
            x3 = __expf(lrelu(el4.w + er4.w)) * i3;
        }
        for (int q = 0; q < cnt; q++) {
            int sj = __shfl_sync(FULLMASK, s, q);
            float w0 = __shfl_sync(FULLMASK, x0, q);
            float w1 = __shfl_sync(FULLMASK, x1, q);
            float w2 = __shfl_sync(FULLMASK, x2, q);
            float w3 = __shfl_sync(FULLMASK, x3, q);
            float w = h == 0 ? w0 : (h == 1 ? w1 : (h == 2 ? w2 : w3));
            float4 f = *(const float4*)(g_feat + (size_t)sj * HD + lane * 4);
            acc.x = fmaf(w, f.x, acc.x);
            acc.y = fmaf(w, f.y, acc.y);
            acc.z = fmaf(w, f.z, acc.z);
            acc.w = fmaf(w, f.w, acc.w);
        }
    }

    float4 bv = *(const float4*)(bias + lane * 4);
    float4 o;
    o.x = fmaxf(acc.x + bv.x, 0.f);
    o.y = fmaxf(acc.y + bv.y, 0.f);
    o.z = fmaxf(acc.z + bv.z, 0.f);
    o.w = fmaxf(acc.w + bv.w, 0.f);
    *(float4*)(g_hbuf + (size_t)node * HD + lane * 4) = o;
}

// ---------------- fused softmax + aggr + head-mean + log_softmax, layer 3 ---
__global__ void aggr47_final_kernel(const float* __restrict__ b3,
                                    float* __restrict__ out) {
    int node = (blockIdx.x * blockDim.x + threadIdx.x) >> 5;
    int lane = threadIdx.x & 31;
    if (node >= NN) return;
    int beg = g_off[node], end = g_off[node + 1];
    int deg = end - beg;
    float4 er4 = *(const float4*)(g_er + (size_t)node * 4);

    int   sc[NCH];
    float x0c[NCH], x1c[NCH], x2c[NCH], x3c[NCH];
    float d0 = 0.f, d1 = 0.f, d2 = 0.f, d3 = 0.f;
    int nch = (deg + 31) >> 5; if (nch > NCH) nch = NCH;

#pragma unroll
    for (int c = 0; c < NCH; c++) {
        sc[c] = 0; x0c[c] = 0.f; x1c[c] = 0.f; x2c[c] = 0.f; x3c[c] = 0.f;
        if (c < nch) {
            int p = beg + c * 32 + lane;
            if (p < end) {
                int s = g_esrc[p]; sc[c] = s;
                float4 el4 = *(const float4*)(g_el + (size_t)s * 4);
                float e0 = __expf(lrelu(el4.x + er4.x));
                float e1 = __expf(lrelu(el4.y + er4.y));
                float e2 = __expf(lrelu(el4.z + er4.z));
                float e3 = __expf(lrelu(el4.w + er4.w));
                x0c[c] = e0; x1c[c] = e1; x2c[c] = e2; x3c[c] = e3;
                d0 += e0; d1 += e1; d2 += e2; d3 += e3;
            }
        }
    }
    for (int p = beg + NCH * 32 + lane; p < end; p += 32) {
        int s = g_esrc[p];
        float4 el4 = *(const float4*)(g_el + (size_t)s * 4);
        d0 += __expf(lrelu(el4.x + er4.x));
        d1 += __expf(lrelu(el4.y + er4.y));
        d2 += __expf(lrelu(el4.z + er4.z));
        d3 += __expf(lrelu(el4.w + er4.w));
    }
    d0 = warpsum(d0); d1 = warpsum(d1); d2 = warpsum(d2); d3 = warpsum(d3);
    float i0 = 1.f / d0, i1 = 1.f / d1, i2 = 1.f / d2, i3 = 1.f / d3;
#pragma unroll
    for (int c = 0; c < NCH; c++) {
        x0c[c] *= i0; x1c[c] *= i1; x2c[c] *= i2; x3c[c] *= i3;
    }

    bool hi = (lane < CC - 32);
    int cx = 32 + lane;
    float a0 = 0.f, a1 = 0.f;
#pragma unroll
    for (int c = 0; c < NCH; c++) {
        if (c < nch) {
            int cnt = min(32, deg - c * 32);
            for (int j = 0; j < cnt; j++) {
                int sj = __shfl_sync(FULLMASK, sc[c], j);
                float w0 = __shfl_sync(FULLMASK, x0c[c], j);
                float w1 = __shfl_sync(FULLMASK, x1c[c], j);
                float w2 = __shfl_sync(FULLMASK, x2c[c], j);
                float w3 = __shfl_sync(FULLMASK, x3c[c], j);
                const float* fr = g_feat + (size_t)sj * HC;
                a0 += w0 * fr[lane] + w1 * fr[CC + lane]
                    + w2 * fr[2 * CC + lane] + w3 * fr[3 * CC + lane];
                if (hi)
                    a1 += w0 * fr[cx] + w1 * fr[CC + cx]
                        + w2 * fr[2 * CC + cx] + w3 * fr[3 * CC + cx];
            }
        }
    }
    for (int base = beg + NCH * 32; base < end; base += 32) {
        int p = base + lane;
        int cnt = min(32, end - base);
        int s = 0; float x0 = 0.f, x1 = 0.f, x2 = 0.f, x3 = 0.f;
        if (p < end) {
            s = g_esrc[p];
            float4 el4 = *(const float4*)(g_el + (size_t)s * 4);
            x0 = __expf(lrelu(el4.x + er4.x)) * i0;
            x1 = __expf(lrelu(el4.y + er4.y)) * i1;
            x2 = __expf(lrelu(el4.z + er4.z)) * i2;
            x3 = __expf(lrelu(el4.w + er4.w)) * i3;
        }
        for (int q = 0; q < cnt; q++) {
            int sj = __shfl_sync(FULLMASK, s, q);
            float w0 = __shfl_sync(FULLMASK, x0, q);
            float w1 = __shfl_sync(FULLMASK, x1, q);
            float w2 = __shfl_sync(FULLMASK, x2, q);
            float w3 = __shfl_sync(FULLMASK, x3, q);
            const float* fr = g_feat + (size_t)sj * HC;
            a0 += w0 * fr[lane] + w1 * fr[CC + lane]
                + w2 * fr[2 * CC + lane] + w3 * fr[3 * CC + lane];
            if (hi)
                a1 += w0 * fr[cx] + w1 * fr[CC + cx]
                    + w2 * fr[2 * CC + cx] + w3 * fr[3 * CC + cx];
        }
    }

    float v0 = a0 * 0.25f + 0.25f * (b3[lane] + b3[CC + lane] +
                                     b3[2 * CC + lane] + b3[3 * CC + lane]);
    float v1 = 0.f;
    if (hi)
        v1 = a1 * 0.25f + 0.25f * (b3[cx] + b3[CC + cx] +
                                   b3[2 * CC + cx] + b3[3 * CC + cx]);
    float mm = v0;
    if (hi) mm = fmaxf(mm, v1);
    mm = warpmax(mm);
    float s = __expf(v0 - mm);
    if (hi) s += __expf(v1 - mm);
    s = warpsum(s);
    float lse = logf(s) + mm;
    out[(size_t)node * CC + lane] = v0 - lse;
    if (hi) out[(size_t)node * CC + cx] = v1 - lse;
}

// ---------------- host orchestration ----------------------------------------
extern "C" void kernel_launch(void* const* d_in, const int* in_sizes, int n_in,
                              void* d_out, int out_size) {
    const float* x   = (const float*)d_in[0];
    const int*   src = (const int*)  d_in[1];
    const int*   dst = (const int*)  d_in[2];
    const float* W1  = (const float*)d_in[3];
    const float* al1 = (const float*)d_in[4];
    const float* ar1 = (const float*)d_in[5];
    const float* b1  = (const float*)d_in[6];
    const float* W2  = (const float*)d_in[7];
    const float* al2 = (const float*)d_in[8];
    const float* ar2 = (const float*)d_in[9];
    const float* b2  = (const float*)d_in[10];
    const float* W3  = (const float*)d_in[11];
    const float* al3 = (const float*)d_in[12];
    const float* ar3 = (const float*)d_in[13];
    const float* b3  = (const float*)d_in[14];
    float* out = (float*)d_out;

    // ---- CSR build: one kernel (zero + hist + scan + scatter) ----
    csr_build_kernel<<<CSRB, CSRT>>>(src, dst);

    int node_warp_blocks = (NN * 32 + 255) / 256;
    int mblocks = (NN + GBM - 1) / GBM;

    // ---- Layer 1: IN -> H*D, ReLU ----
    tf32_gemm_kernel<<<dim3(2, mblocks), 256>>>(x, W1, NN, IN_F, HD, 0);
    elr_kernel<<<node_warp_blocks, 256>>>(al1, ar1, DD);
    aggr128_kernel<<<node_warp_blocks, 256>>>(b1);

    // ---- Layer 2: H*D -> H*D, ReLU ----
    tf32_gemm_kernel<<<dim3(2, mblocks), 256>>>(nullptr, W2, NN, HD, HD, 1);
    elr_kernel<<<node_warp_blocks, 256>>>(al2, ar2, DD);
    aggr128_kernel<<<node_warp_blocks, 256>>>(b2);

    // ---- Layer 3: H*D -> H*C, head-mean + log_softmax ----
    tf32_gemm_kernel<<<dim3(3, mblocks), 256>>>(nullptr, W3, NN, HD, HC, 1);
    elr_kernel<<<node_warp_blocks, 256>>>(al3, ar3, CC);
    aggr47_final_kernel<<<node_warp_blocks, 256>>>(b3, out);
}

// round 12
// speedup vs baseline: 1.5707x; 1.0669x over previous
#include <cuda_runtime.h>
#include <math.h>
#include <float.h>

#define NN 100000
#define EE 1600000
#define IN_F 256
#define HH 4
#define DD 32
#define CC 47
#define HD 128        // H*D
#define HC 188        // H*C
#define NEG_SLOPE 0.2f
#define FULLMASK 0xffffffffu

// ---------------- scratch (static device globals; no allocation) ------------
__device__ __align__(16) float g_feat[(size_t)NN * HC];
__device__ __align__(16) float g_hbuf[(size_t)NN * HD];
__device__ __align__(16) float g_el[NN * HH];
__device__ __align__(16) float g_er[NN * HH];
__device__ int g_deg[NN];
__device__ int g_off[NN + 1];
__device__ int g_cur[NN];
__device__ int g_esrc[EE];
__device__ unsigned g_barcnt[8];
__device__ int g_chunksum[512];
__device__ int g_chunkoff[512];

// ---------------- warp helpers ----------------------------------------------
__device__ __forceinline__ float warpsum(float v) {
#pragma unroll
    for (int o = 16; o; o >>= 1) v += __shfl_xor_sync(FULLMASK, v, o);
    return v;
}
__device__ __forceinline__ float warpmax(float v) {
#pragma unroll
    for (int o = 16; o; o >>= 1) v = fmaxf(v, __shfl_xor_sync(FULLMASK, v, o));
    return v;
}
__device__ __forceinline__ float lrelu(float v) {
    return v > 0.f ? v : NEG_SLOPE * v;
}
__device__ __forceinline__ unsigned f2tf(float x) {
    unsigned r;
    asm("cvt.rna.tf32.f32 %0, %1;" : "=r"(r) : "f"(x));
    return r;
}

// ---------------- single-kernel CSR build ------------------------------------
#define CSRB 592
#define CSRT 256

__device__ __forceinline__ void grid_barrier(int slot) {
    __threadfence();
    __syncthreads();
    if (threadIdx.x == 0) {
        unsigned ticket = atomicAdd(&g_barcnt[slot], 1u) + 1u;
        unsigned tgt = ((ticket + CSRB - 1u) / CSRB) * CSRB;
        while (*((volatile unsigned*)&g_barcnt[slot]) < tgt) __nanosleep(64);
    }
    __syncthreads();
}

__global__ void __launch_bounds__(CSRT)
csr_build_kernel(const int* __restrict__ src, const int* __restrict__ dst) {
    __shared__ int ws[8];
    __shared__ int carry_s;
    int tid = threadIdx.x, bid = blockIdx.x;
    int gtid = bid * CSRT + tid;
    const int gstride = CSRB * CSRT;
    const int NCHUNK = (NN + CSRT - 1) / CSRT;
    int lane = tid & 31, wid = tid >> 5;

    for (int i = gtid; i < NN; i += gstride) g_deg[i] = 0;
    grid_barrier(0);

    for (int e = gtid; e < EE; e += gstride) atomicAdd(&g_deg[dst[e]], 1);
    grid_barrier(1);

    if (bid < NCHUNK) {
        int i = bid * CSRT + tid;
        int v = (i < NN) ? __ldcg(&g_deg[i]) : 0;
        int x = v;
#pragma unroll
        for (int o = 1; o < 32; o <<= 1) {
            int t = __shfl_up_sync(FULLMASK, x, o);
            if (lane >= o) x += t;
        }
        if (lane == 31) ws[wid] = x;
        __syncthreads();
        if (wid == 0 && lane < 8) {
            int w = ws[lane];
#pragma unroll
            for (int o = 1; o < 8; o <<= 1) {
                int t = __shfl_up_sync(0xffu, w, o);
                if (lane >= o) w += t;
            }
            ws[lane] = w;
        }
        __syncthreads();
        int woff = wid ? ws[wid - 1] : 0;
        int incl = x + woff;
        if (i < NN) g_off[i] = incl - v;
        if (tid == CSRT - 1) g_chunksum[bid] = incl;
    }
    grid_barrier(2);

    if (bid == 0) {
        if (tid == 0) carry_s = 0;
        __syncthreads();
        for (int base = 0; base < NCHUNK; base += CSRT) {
            int i = base + tid;
            int v = (i < NCHUNK) ? __ldcg(&g_chunksum[i]) : 0;
            int x = v;
#pragma unroll
            for (int o = 1; o < 32; o <<= 1) {
                int t = __shfl_up_sync(FULLMASK, x, o);
                if (lane >= o) x += t;
            }
            if (lane == 31) ws[wid] = x;
            __syncthreads();
            if (wid == 0 && lane < 8) {
                int w = ws[lane];
#pragma unroll
                for (int o = 1; o < 8; o <<= 1) {
                    int t = __shfl_up_sync(0xffu, w, o);
                    if (lane >= o) w += t;
                }
                ws[lane] = w;
            }
            __syncthreads();
            int woff = wid ? ws[wid - 1] : 0;
            int incl = x + woff;
            int carry = carry_s;
            if (i < NCHUNK) g_chunkoff[i] = carry + incl - v;
            __syncthreads();
            if (tid == CSRT - 1) carry_s = carry + incl;
            __syncthreads();
        }
        if (tid == 0) g_off[NN] = carry_s;
    }
    grid_barrier(3);

    if (bid < NCHUNK) {
        int i = bid * CSRT + tid;
        if (i < NN) {
            int off = __ldcg(&g_chunkoff[bid]);
            int e = g_off[i] + off;
            g_off[i] = e;
            g_cur[i] = e;
        }
    }
    grid_barrier(4);

    for (int e = gtid; e < EE; e += gstride) {
        int p = atomicAdd(&g_cur[dst[e]], 1);
        g_esrc[p] = src[e];
    }
}

// ---------------- 3xTF32 tensor-core GEMM -----------------------------------
// permute != 0 (layer 3): output column oc = h*CC + c is stored at row offset
// c*HH + h (class-major layout) for vectorized aggregation loads.
#define GBM 128
#define GBN 64
#define GBK 16
#define ASTR (GBM + 8)
#define BSTR (GBN + 8)

__device__ __forceinline__ void mma_tf32(float* c, const unsigned* a, const unsigned* b) {
    asm("mma.sync.aligned.m16n8k8.row.col.f32.tf32.tf32.f32 "
        "{%0,%1,%2,%3}, {%4,%5,%6,%7}, {%8,%9}, {%0,%1,%2,%3};"
        : "+f"(c[0]), "+f"(c[1]), "+f"(c[2]), "+f"(c[3])
        : "r"(a[0]), "r"(a[1]), "r"(a[2]), "r"(a[3]), "r"(b[0]), "r"(b[1]));
}

__global__ void __launch_bounds__(256, 2)
tf32_gemm_kernel(const float* __restrict__ Aext,
                 const float* __restrict__ B,
                 int M, int K, int Kn, int use_hbuf, int permute) {
    __shared__ unsigned Ah[GBK][ASTR], Al[GBK][ASTR];
    __shared__ unsigned Bh[GBK][BSTR], Bl[GBK][BSTR];

    const float* __restrict__ A = use_hbuf ? (const float*)g_hbuf : Aext;

    int tid = threadIdx.x;
    int wid = tid >> 5, lane = tid & 31;
    int row0 = blockIdx.y * GBM, col0 = blockIdx.x * GBN;
    int m0 = (wid >> 1) * 32;
    int n0 = (wid & 1) * 32;
    int gq = lane >> 2;
    int tg = lane & 3;

    int a_m = tid >> 1;
    int a_k = (tid & 1) * 8;
    int b_k = tid >> 4;
    int b_n = (tid & 15) * 4;

    float aS[8];
    float bS[4];

    auto loadG = [&](int k0) {
        int row = row0 + a_m;
        if (row < M) {
            const float* ap = A + (size_t)row * K + k0 + a_k;
            float4 v0 = *(const float4*)(ap);
            float4 v1 = *(const float4*)(ap + 4);
            aS[0] = v0.x; aS[1] = v0.y; aS[2] = v0.z; aS[3] = v0.w;
            aS[4] = v1.x; aS[5] = v1.y; aS[6] = v1.z; aS[7] = v1.w;
        } else {
#pragma unroll
            for (int j = 0; j < 8; j++) aS[j] = 0.f;
        }
        int col = col0 + b_n;
        const float* bp = B + (size_t)(k0 + b_k) * Kn;
        if (col + 3 < Kn) {
            float4 v = *(const float4*)(bp + col);
            bS[0] = v.x; bS[1] = v.y; bS[2] = v.z; bS[3] = v.w;
        } else {
#pragma unroll
            for (int j = 0; j < 4; j++) bS[j] = (col + j < Kn) ? bp[col + j] : 0.f;
        }
    };
    auto storeS = [&]() {
#pragma unroll
        for (int j = 0; j < 8; j++) {
            unsigned h = f2tf(aS[j]);
            Ah[a_k + j][a_m] = h;
            Al[a_k + j][a_m] = f2tf(aS[j] - __uint_as_float(h));
        }
#pragma unroll
        for (int j = 0; j < 4; j++) {
            unsigned h = f2tf(bS[j]);
            Bh[b_k][b_n + j] = h;
            Bl[b_k][b_n + j] = f2tf(bS[j] - __uint_as_float(h));
        }
    };

    float acc[2][4][4];
#pragma unroll
    for (int mi = 0; mi < 2; mi++)
#pragma unroll
        for (int ni = 0; ni < 4; ni++)
#pragma unroll
            for (int r = 0; r < 4; r++) acc[mi][ni][r] = 0.f;

    loadG(0);
    storeS();
    __syncthreads();

    for (int k0 = 0; k0 < K; k0 += GBK) {
        bool more = (k0 + GBK < K);
        if (more) loadG(k0 + GBK);
#pragma unroll
        for (int kk = 0; kk < GBK; kk += 8) {
            unsigned aHf[2][4], aLf[2][4];
#pragma unroll
            for (int mi = 0; mi < 2; mi++) {
                int mr = m0 + mi * 16 + gq;
                aHf[mi][0] = Ah[kk + tg][mr];
                aHf[mi][1] = Ah[kk + tg][mr + 8];
                aHf[mi][2] = Ah[kk + 4 + tg][mr];
                aHf[mi][3] = Ah[kk + 4 + tg][mr + 8];
                aLf[mi][0] = Al[kk + tg][mr];
                aLf[mi][1] = Al[kk + tg][mr + 8];
                aLf[mi][2] = Al[kk + 4 + tg][mr];
                aLf[mi][3] = Al[kk + 4 + tg][mr + 8];
            }
            unsigned bHf[4][2], bLf[4][2];
#pragma unroll
            for (int ni = 0; ni < 4; ni++) {
                int bc = n0 + ni * 8 + gq;
                bHf[ni][0] = Bh[kk + tg][bc];
                bHf[ni][1] = Bh[kk + 4 + tg][bc];
                bLf[ni][0] = Bl[kk + tg][bc];
                bLf[ni][1] = Bl[kk + 4 + tg][bc];
            }
#pragma unroll
            for (int mi = 0; mi < 2; mi++)
#pragma unroll
                for (int ni = 0; ni < 4; ni++) {
                    mma_tf32(acc[mi][ni], aHf[mi], bHf[ni]);
                    mma_tf32(acc[mi][ni], aHf[mi], bLf[ni]);
                    mma_tf32(acc[mi][ni], aLf[mi], bHf[ni]);
                }
        }
        if (more) {
            __syncthreads();
            storeS();
            __syncthreads();
        }
    }

#pragma unroll
    for (int mi = 0; mi < 2; mi++) {
        int r0 = row0 + m0 + mi * 16 + gq;
#pragma unroll
        for (int ni = 0; ni < 4; ni++) {
            int c = col0 + n0 + ni * 8 + tg * 2;
            if (permute) {
#pragma unroll
                for (int rr = 0; rr < 2; rr++) {
                    int row = r0 + rr * 8;
                    if (row < M) {
#pragma unroll
                        for (int cc = 0; cc < 2; cc++) {
                            int oc = c + cc;
                            if (oc < Kn) {
                                int hh = oc / CC, ccl = oc - hh * CC;
                                g_feat[(size_t)row * HC + ccl * HH + hh] =
                                    acc[mi][ni][rr * 2 + cc];
                            }
                        }
                    }
                }
            } else if (c < Kn) {
                if (r0 < M) {
                    float2 v = make_float2(acc[mi][ni][0], acc[mi][ni][1]);
                    *(float2*)(g_feat + (size_t)r0 * Kn + c) = v;
                }
                if (r0 + 8 < M) {
                    float2 v = make_float2(acc[mi][ni][2], acc[mi][ni][3]);
                    *(float2*)(g_feat + (size_t)(r0 + 8) * Kn + c) = v;
                }
            }
        }
    }
}

// ---------------- per-node attention projections (el, er) -------------------
// warp per node; lane -> head h = lane>>3, 8 lanes per head.
// perm != 0: feat row is class-major [c*HH + h] (layer 3 layout).
__global__ void elr_kernel(const float* __restrict__ al,
                           const float* __restrict__ ar,
                           int F, int perm) {
    int w = (blockIdx.x * blockDim.x + threadIdx.x) >> 5;
    int lane = threadIdx.x & 31;
    if (w >= NN) return;
    int h = lane >> 3, j = lane & 7;
    const float* frow = g_feat + (size_t)w * HH * F;
    const float* alh = al + h * F;
    const float* arh = ar + h * F;
    float sl = 0.f, sr = 0.f;
    if (perm) {
        for (int d = j; d < F; d += 8) {
            float f = frow[d * HH + h];
            sl = fmaf(f, alh[d], sl);
            sr = fmaf(f, arh[d], sr);
        }
    } else {
        const float* fh = frow + h * F;
        for (int d = j; d < F; d += 8) {
            float f = fh[d];
            sl = fmaf(f, alh[d], sl);
            sr = fmaf(f, arh[d], sr);
        }
    }
#pragma unroll
    for (int o = 4; o; o >>= 1) {
        sl += __shfl_xor_sync(FULLMASK, sl, o);
        sr += __shfl_xor_sync(FULLMASK, sr, o);
    }
    if (j == 0) {
        g_el[w * HH + h] = sl;
        g_er[w * HH + h] = sr;
    }
}

// ---------------- fused softmax + aggregation, layers 1/2 (HF=128) ----------
// One warp per dst node. Alphas cached in registers (deg <= 64) and
// head-transposed so the gather loop needs only 2 shuffles per edge.
#define NCH 2
__global__ void aggr128_kernel(const float* __restrict__ bias) {
    int node = (blockIdx.x * blockDim.x + threadIdx.x) >> 5;
    int lane = threadIdx.x & 31;
    if (node >= NN) return;
    int beg = g_off[node], end = g_off[node + 1];
    int deg = end - beg;
    float4 er4 = *(const float4*)(g_er + (size_t)node * 4);
    int nch = (deg + 31) >> 5; if (nch > NCH) nch = NCH;

    int   sc[NCH];
    float x0c[NCH], x1c[NCH], x2c[NCH], x3c[NCH];
    float d0 = 0.f, d1 = 0.f, d2 = 0.f, d3 = 0.f;
#pragma unroll
    for (int c = 0; c < NCH; c++) {
        sc[c] = 0; x0c[c] = 0.f; x1c[c] = 0.f; x2c[c] = 0.f; x3c[c] = 0.f;
        if (c < nch) {
            int p = beg + c * 32 + lane;
            if (p < end) {
                int s = g_esrc[p]; sc[c] = s;
                float4 el4 = *(const float4*)(g_el + (size_t)s * 4);
                float e0 = __expf(lrelu(el4.x + er4.x));
                float e1 = __expf(lrelu(el4.y + er4.y));
                float e2 = __expf(lrelu(el4.z + er4.z));
                float e3 = __expf(lrelu(el4.w + er4.w));
                x0c[c] = e0; x1c[c] = e1; x2c[c] = e2; x3c[c] = e3;
                d0 += e0; d1 += e1; d2 += e2; d3 += e3;
            }
        }
    }
    for (int p = beg + NCH * 32 + lane; p < end; p += 32) {
        int s = g_esrc[p];
        float4 el4 = *(const float4*)(g_el + (size_t)s * 4);
        d0 += __expf(lrelu(el4.x + er4.x));
        d1 += __expf(lrelu(el4.y + er4.y));
        d2 += __expf(lrelu(el4.z + er4.z));
        d3 += __expf(lrelu(el4.w + er4.w));
    }
    d0 = warpsum(d0); d1 = warpsum(d1); d2 = warpsum(d2); d3 = warpsum(d3);
    float i0 = 1.f / d0, i1 = 1.f / d1, i2 = 1.f / d2, i3 = 1.f / d3;
#pragma unroll
    for (int c = 0; c < NCH; c++) {
        x0c[c] *= i0; x1c[c] *= i1; x2c[c] *= i2; x3c[c] *= i3;
    }

    // head transpose: lane (8h+m) gets y[c][q] = alpha[h][edge 8q+m of chunk c]
    int h = lane >> 3;
    int m = lane & 7;
    int h8 = lane & 24;
    float y[NCH][4];
#pragma unroll
    for (int c = 0; c < NCH; c++) {
#pragma unroll
        for (int q = 0; q < 4; q++) {
            int srcl = q * 8 + m;
            float t0 = __shfl_sync(FULLMASK, x0c[c], srcl);
            float t1 = __shfl_sync(FULLMASK, x1c[c], srcl);
            float t2 = __shfl_sync(FULLMASK, x2c[c], srcl);
            float t3 = __shfl_sync(FULLMASK, x3c[c], srcl);
            y[c][q] = h == 0 ? t0 : (h == 1 ? t1 : (h == 2 ? t2 : t3));
        }
    }

    // gather: 2 shuffles per edge (src index + own-head weight)
    float4 acc = make_float4(0.f, 0.f, 0.f, 0.f);
#pragma unroll
    for (int c = 0; c < NCH; c++) {
        if (c < nch) {
            int cnt = min(32, deg - c * 32);
#pragma unroll
            for (int g = 0; g < 4; g++) {
                int jbase = g * 8;
                if (jbase < cnt) {
                    int gm = min(8, cnt - jbase);
                    for (int mm = 0; mm < gm; mm++) {
                        int sj = __shfl_sync(FULLMASK, sc[c], jbase + mm);
                        float w = __shfl_sync(FULLMASK, y[c][g], h8 + mm);
                        float4 f = *(const float4*)(g_feat + (size_t)sj * HD + lane * 4);
                        acc.x = fmaf(w, f.x, acc.x);
                        acc.y = fmaf(w, f.y, acc.y);
                        acc.z = fmaf(w, f.z, acc.z);
                        acc.w = fmaf(w, f.w, acc.w);
                    }
                }
            }
        }
    }
    // tail: deg > 64 (astronomically rare) — recompute alphas via shfl
    for (int base = beg + NCH * 32; base < end; base += 32) {
        int p = base + lane;
        int cnt = min(32, end - base);
        int s = 0; float x0 = 0.f, x1 = 0.f, x2 = 0.f, x3 = 0.f;
        if (p < end) {
            s = g_esrc[p];
            float4 el4 = *(const float4*)(g_el + (size_t)s * 4);
            x0 = __expf(lrelu(el4.x + er4.x)) * i0;
            x1 = __expf(lrelu(el4.y + er4.y)) * i1;
            x2 = __expf(lrelu(el4.z + er4.z)) * i2;
            x3 = __expf(lrelu(el4.w + er4.w)) * i3;
        }
        for (int q = 0; q < cnt; q++) {
            int sj = __shfl_sync(FULLMASK, s, q);
            float w0 = __shfl_sync(FULLMASK, x0, q);
            float w1 = __shfl_sync(FULLMASK, x1, q);
            float w2 = __shfl_sync(FULLMASK, x2, q);
            float w3 = __shfl_sync(FULLMASK, x3, q);
            float w = h == 0 ? w0 : (h == 1 ? w1 : (h == 2 ? w2 : w3));
            float4 f = *(const float4*)(g_feat + (size_t)sj * HD + lane * 4);
            acc.x = fmaf(w, f.x, acc.x);
            acc.y = fmaf(w, f.y, acc.y);
            acc.z = fmaf(w, f.z, acc.z);
            acc.w = fmaf(w, f.w, acc.w);
        }
    }

    float4 bv = *(const float4*)(bias + lane * 4);
    float4 o;
    o.x = fmaxf(acc.x + bv.x, 0.f);
    o.y = fmaxf(acc.y + bv.y, 0.f);
    o.z = fmaxf(acc.z + bv.z, 0.f);
    o.w = fmaxf(acc.w + bv.w, 0.f);
    *(float4*)(g_hbuf + (size_t)node * HD + lane * 4) = o;
}

// ---------------- fused softmax + aggr + head-mean + log_softmax, layer 3 ---
// feat is class-major [c*HH + h]: per edge, 2 float4 loads give all 4 heads
// for the lane's two classes.
__global__ void aggr47_final_kernel(const float* __restrict__ b3,
                                    float* __restrict__ out) {
    int node = (blockIdx.x * blockDim.x + threadIdx.x) >> 5;
    int lane = threadIdx.x & 31;
    if (node >= NN) return;
    int beg = g_off[node], end = g_off[node + 1];
    int deg = end - beg;
    float4 er4 = *(const float4*)(g_er + (size_t)node * 4);
    int nch = (deg + 31) >> 5; if (nch > NCH) nch = NCH;

    int   sc[NCH];
    float x0c[NCH], x1c[NCH], x2c[NCH], x3c[NCH];
    float d0 = 0.f, d1 = 0.f, d2 = 0.f, d3 = 0.f;
#pragma unroll
    for (int c = 0; c < NCH; c++) {
        sc[c] = 0; x0c[c] = 0.f; x1c[c] = 0.f; x2c[c] = 0.f; x3c[c] = 0.f;
        if (c < nch) {
            int p = beg + c * 32 + lane;
            if (p < end) {
                int s = g_esrc[p]; sc[c] = s;
                float4 el4 = *(const float4*)(g_el + (size_t)s * 4);
                float e0 = __expf(lrelu(el4.x + er4.x));
                float e1 = __expf(lrelu(el4.y + er4.y));
                float e2 = __expf(lrelu(el4.z + er4.z));
                float e3 = __expf(lrelu(el4.w + er4.w));
                x0c[c] = e0; x1c[c] = e1; x2c[c] = e2; x3c[c] = e3;
                d0 += e0; d1 += e1; d2 += e2; d3 += e3;
            }
        }
    }
    for (int p = beg + NCH * 32 + lane; p < end; p += 32) {
        int s = g_esrc[p];
        float4 el4 = *(const float4*)(g_el + (size_t)s * 4);
        d0 += __expf(lrelu(el4.x + er4.x));
        d1 += __expf(lrelu(el4.y + er4.y));
        d2 += __expf(lrelu(el4.z + er4.z));
        d3 += __expf(lrelu(el4.w + er4.w));
    }
    d0 = warpsum(d0); d1 = warpsum(d1); d2 = warpsum(d2); d3 = warpsum(d3);
    float i0 = 1.f / d0, i1 = 1.f / d1, i2 = 1.f / d2, i3 = 1.f / d3;
#pragma unroll
    for (int c = 0; c < NCH; c++) {
        x0c[c] *= i0; x1c[c] *= i1; x2c[c] *= i2; x3c[c] *= i3;
    }

    bool hi = (lane < CC - 32);
    int cx = 32 + lane;
    float a0 = 0.f, a1 = 0.f;
#pragma unroll
    for (int c = 0; c < NCH; c++) {
        if (c < nch) {
            int cnt = min(32, deg - c * 32);
            for (int j = 0; j < cnt; j++) {
                int sj = __shfl_sync(FULLMASK, sc[c], j);
                float w0 = __shfl_sync(FULLMASK, x0c[c], j);
                float w1 = __shfl_sync(FULLMASK, x1c[c], j);
                float w2 = __shfl_sync(FULLMASK, x2c[c], j);
                float w3 = __shfl_sync(FULLMASK, x3c[c], j);
                const float* fr = g_feat + (size_t)sj * HC;
                float4 f0 = *(const float4*)(fr + lane * 4);
                a0 += w0 * f0.x + w1 * f0.y + w2 * f0.z + w3 * f0.w;
                if (hi) {
                    float4 f1 = *(const float4*)(fr + cx * 4);
                    a1 += w0 * f1.x + w1 * f1.y + w2 * f1.z + w3 * f1.w;
                }
            }
        }
    }
    for (int base = beg + NCH * 32; base < end; base += 32) {
        int p = base + lane;
        int cnt = min(32, end - base);
        int s = 0; float x0 = 0.f, x1 = 0.f, x2 = 0.f, x3 = 0.f;
        if (p < end) {
            s = g_esrc[p];
            float4 el4 = *(const float4*)(g_el + (size_t)s * 4);
            x0 = __expf(lrelu(el4.x + er4.x)) * i0;
            x1 = __expf(lrelu(el4.y + er4.y)) * i1;
            x2 = __expf(lrelu(el4.z + er4.z)) * i2;
            x3 = __expf(lrelu(el4.w + er4.w)) * i3;
        }
        for (int q = 0; q < cnt; q++) {
            int sj = __shfl_sync(FULLMASK, s, q);
            float w0 = __shfl_sync(FULLMASK, x0, q);
            float w1 = __shfl_sync(FULLMASK, x1, q);
            float w2 = __shfl_sync(FULLMASK, x2, q);
            float w3 = __shfl_sync(FULLMASK, x3, q);
            const float* fr = g_feat + (size_t)sj * HC;
            float4 f0 = *(const float4*)(fr + lane * 4);
            a0 += w0 * f0.x + w1 * f0.y + w2 * f0.z + w3 * f0.w;
            if (hi) {
                float4 f1 = *(const float4*)(fr + cx * 4);
                a1 += w0 * f1.x + w1 * f1.y + w2 * f1.z + w3 * f1.w;
            }
        }
    }

    float v0 = a0 * 0.25f + 0.25f * (b3[lane] + b3[CC + lane] +
                                     b3[2 * CC + lane] + b3[3 * CC + lane]);
    float v1 = 0.f;
    if (hi)
        v1 = a1 * 0.25f + 0.25f * (b3[cx] + b3[CC + cx] +
                                   b3[2 * CC + cx] + b3[3 * CC + cx]);
    float mm = v0;
    if (hi) mm = fmaxf(mm, v1);
    mm = warpmax(mm);
    float s = __expf(v0 - mm);
    if (hi) s += __expf(v1 - mm);
    s = warpsum(s);
    float lse = logf(s) + mm;
    out[(size_t)node * CC + lane] = v0 - lse;
    if (hi) out[(size_t)node * CC + cx] = v1 - lse;
}

// ---------------- host orchestration ----------------------------------------
extern "C" void kernel_launch(void* const* d_in, const int* in_sizes, int n_in,
                              void* d_out, int out_size) {
    const float* x   = (const float*)d_in[0];
    const int*   src = (const int*)  d_in[1];
    const int*   dst = (const int*)  d_in[2];
    const float* W1  = (const float*)d_in[3];
    const float* al1 = (const float*)d_in[4];
    const float* ar1 = (const float*)d_in[5];
    const float* b1  = (const float*)d_in[6];
    const float* W2  = (const float*)d_in[7];
    const float* al2 = (const float*)d_in[8];
    const float* ar2 = (const float*)d_in[9];
    const float* b2  = (const float*)d_in[10];
    const float* W3  = (const float*)d_in[11];
    const float* al3 = (const float*)d_in[12];
    const float* ar3 = (const float*)d_in[13];
    const float* b3  = (const float*)d_in[14];
    float* out = (float*)d_out;

    // ---- CSR build: one kernel (zero + hist + scan + scatter) ----
    csr_build_kernel<<<CSRB, CSRT>>>(src, dst);

    int node_warp_blocks = (NN * 32 + 255) / 256;
    int mblocks = (NN + GBM - 1) / GBM;

    // ---- Layer 1: IN -> H*D, ReLU ----
    tf32_gemm_kernel<<<dim3(2, mblocks), 256>>>(x, W1, NN, IN_F, HD, 0, 0);
    elr_kernel<<<node_warp_blocks, 256>>>(al1, ar1, DD, 0);
    aggr128_kernel<<<node_warp_blocks, 256>>>(b1);

    // ---- Layer 2: H*D -> H*D, ReLU ----
    tf32_gemm_kernel<<<dim3(2, mblocks), 256>>>(nullptr, W2, NN, HD, HD, 1, 0);
    elr_kernel<<<node_warp_blocks, 256>>>(al2, ar2, DD, 0);
    aggr128_kernel<<<node_warp_blocks, 256>>>(b2);

    // ---- Layer 3: H*D -> H*C (class-major), head-mean + log_softmax ----
    tf32_gemm_kernel<<<dim3(3, mblocks), 256>>>(nullptr, W3, NN, HD, HC, 1, 1);
    elr_kernel<<<node_warp_blocks, 256>>>(al3, ar3, CC, 1);
    aggr47_final_kernel<<<node_warp_blocks, 256>>>(b3, out);
}